// round 5
// baseline (speedup 1.0000x reference)
#include <cuda_runtime.h>
#include <math.h>

// ---------------- problem dims ----------------
#define NTOK   16384      // B*S
#define DIMD   256        // D
#define HID    512        // H
#define SEQ    512        // S
#define BATCH  32
#define NHEAD  8
#define HDIM   64
#define PFF    2048
#define NLAYER 2
#define NMAXC  15

// ---------------- scratch (static device globals; no allocation) -------------
__device__ float g_x [NTOK * DIMD];            // pre-social embedded x
__device__ float g_xs[NTOK * DIMD];            // post-social x (output #2)
__device__ float g_h [NTOK * HID];
__device__ float g_q [NTOK * HID];
__device__ float g_k [NTOK * HID];
__device__ float g_v [NTOK * HID];
__device__ float g_o [NTOK * HID];
__device__ float g_t [NTOK * HID];
__device__ float g_ff[NTOK * PFF];
__device__ float g_e [(size_t)BATCH * NHEAD * SEQ * SEQ]; // attention scores/probs

// ---------------- reductions ----------------
__device__ __forceinline__ float block_sum(float v, float* red) {
    int lane = threadIdx.x & 31, w = threadIdx.x >> 5;
    int nw = blockDim.x >> 5;
#pragma unroll
    for (int o = 16; o > 0; o >>= 1) v += __shfl_xor_sync(0xffffffffu, v, o);
    if (lane == 0) red[w] = v;
    __syncthreads();
    if (w == 0) {
        float t = (lane < nw) ? red[lane] : 0.f;
#pragma unroll
        for (int o = 16; o > 0; o >>= 1) t += __shfl_xor_sync(0xffffffffu, t, o);
        if (lane == 0) red[0] = t;
    }
    __syncthreads();
    float r = red[0];
    __syncthreads();
    return r;
}

__device__ __forceinline__ float block_max(float v, float* red) {
    int lane = threadIdx.x & 31, w = threadIdx.x >> 5;
    int nw = blockDim.x >> 5;
#pragma unroll
    for (int o = 16; o > 0; o >>= 1) v = fmaxf(v, __shfl_xor_sync(0xffffffffu, v, o));
    if (lane == 0) red[w] = v;
    __syncthreads();
    if (w == 0) {
        float t = (lane < nw) ? red[lane] : -3.0e38f;
#pragma unroll
        for (int o = 16; o > 0; o >>= 1) t = fmaxf(t, __shfl_xor_sync(0xffffffffu, t, o));
        if (lane == 0) red[0] = t;
    }
    __syncthreads();
    float r = red[0];
    __syncthreads();
    return r;
}

// ---------------- 1. embedding + PE + time encoding ----------------
__global__ void embed_kernel(const int* __restrict__ src,
                             const float* __restrict__ tint,
                             const float* __restrict__ emb,
                             const float* __restrict__ timeW,
                             const float* __restrict__ timeb) {
    int n = blockIdx.x;          // token
    int d = threadIdx.x;         // 0..255
    int s = n % SEQ;
    int tok = src[n];
    // sinusoidal PE computed in double (robust to fast-math sinf at args ~511 rad)
    double div = exp((double)((d >> 1) << 1) * (-9.210340371976184 / 256.0));
    double arg = (double)s * div;
    float pe = (d & 1) ? (float)cos(arg) : (float)sin(arg);
    g_x[n * DIMD + d] = emb[(size_t)tok * DIMD + d] + pe + tint[n] * timeW[d] + timeb[d];
}

// ---------------- 2. neighbor aggregation + social block ----------------
__global__ void social_kernel(const int* __restrict__ src,
                              const int* __restrict__ nidx,
                              const int* __restrict__ ncnt,
                              const float* __restrict__ W,
                              const float* __restrict__ bvec,
                              const float* __restrict__ gvec,
                              const float* __restrict__ beta) {
    int n = blockIdx.x;
    int d = threadIdx.x;         // 0..255
    __shared__ float agg[DIMD];
    __shared__ float red[32];

    int cnt = ncnt[n];
    float xf = g_x[n * DIMD + d];
    float a = 0.f;
    for (int j = 0; j < cnt; j++) {
        int m = nidx[n * NMAXC + j];
        a += g_x[m * DIMD + d];
    }
    a /= (float)(cnt > 0 ? cnt : 1);
    agg[d] = a;
    __syncthreads();

    float z = xf + bvec[d];
#pragma unroll 4
    for (int k = 0; k < DIMD; k++) z = fmaf(agg[k], W[k * DIMD + d], z);

    float mu = block_sum(z, red) * (1.0f / DIMD);
    float c = z - mu;
    float var = block_sum(c * c, red) * (1.0f / DIMD);
    float ln = c * rsqrtf(var + 1e-5f) * gvec[d] + beta[d];
    float soc = fmaxf(ln, 0.f);
    if (cnt <= 0) soc = xf;
    if (src[n] == 0) soc = 0.f;       // PAD token
    g_xs[n * DIMD + d] = xf + 0.2f * soc;
}

// ---------------- generic SGEMM: C[M,N] = A[M,K]@B[K,N] + bias (+relu) -------
// 64x64 tile, 256 threads, 4x4 per thread, BK=16
__global__ void sgemm_kernel(const float* __restrict__ A,
                             const float* __restrict__ B,
                             const float* __restrict__ bias,
                             float* __restrict__ C,
                             int M, int N, int K, int relu) {
    __shared__ float As[16][64];
    __shared__ float Bs[16][64];
    int bn = blockIdx.x * 64, bm = blockIdx.y * 64;
    int tid = threadIdx.x;
    int tx = tid & 15, ty = tid >> 4;
    float acc[4][4];
#pragma unroll
    for (int i = 0; i < 4; i++)
#pragma unroll
        for (int j = 0; j < 4; j++) acc[i][j] = 0.f;

    const float* Ab = A + (size_t)bm * K;
    const float* Bb = B + bn;
    for (int k0 = 0; k0 < K; k0 += 16) {
#pragma unroll
        for (int i = 0; i < 4; i++) {
            int idx = tid + i * 256;
            int m = idx >> 4, kk = idx & 15;
            As[kk][m] = Ab[(size_t)m * K + k0 + kk];
        }
#pragma unroll
        for (int i = 0; i < 4; i++) {
            int idx = tid + i * 256;
            int kk = idx >> 6, nn = idx & 63;
            Bs[kk][nn] = Bb[(size_t)(k0 + kk) * N + nn];
        }
        __syncthreads();
#pragma unroll
        for (int kk = 0; kk < 16; kk++) {
            float a[4], bv[4];
#pragma unroll
            for (int i = 0; i < 4; i++) a[i] = As[kk][ty * 4 + i];
#pragma unroll
            for (int j = 0; j < 4; j++) bv[j] = Bs[kk][tx * 4 + j];
#pragma unroll
            for (int i = 0; i < 4; i++)
#pragma unroll
                for (int j = 0; j < 4; j++) acc[i][j] = fmaf(a[i], bv[j], acc[i][j]);
        }
        __syncthreads();
    }
#pragma unroll
    for (int i = 0; i < 4; i++) {
        int m = bm + ty * 4 + i;
#pragma unroll
        for (int j = 0; j < 4; j++) {
            int n = bn + tx * 4 + j;
            float v = acc[i][j] + bias[n];
            if (relu) v = fmaxf(v, 0.f);
            C[(size_t)m * N + n] = v;
        }
    }
}

// ---------------- attention scores: e[bh,q,k] = Q.Kt / 8 ----------------
__global__ void score_kernel() {
    int bh = blockIdx.z;
    int b = bh >> 3, hh = bh & 7;
    int bm = blockIdx.y * 64, bn = blockIdx.x * 64;
    __shared__ float Qs[64][65];
    __shared__ float Ks[64][65];
    int tid = threadIdx.x;
    int tx = tid & 15, ty = tid >> 4;
    const float* Qp = g_q + (size_t)(b * SEQ) * HID + hh * HDIM;
    const float* Kp = g_k + (size_t)(b * SEQ) * HID + hh * HDIM;
#pragma unroll
    for (int i = 0; i < 16; i++) {
        int idx = tid + i * 256;      // 4096 elems
        int r = idx >> 6, dd = idx & 63;
        Qs[dd][r] = Qp[(size_t)(bm + r) * HID + dd];
        Ks[dd][r] = Kp[(size_t)(bn + r) * HID + dd];
    }
    __syncthreads();
    float acc[4][4];
#pragma unroll
    for (int i = 0; i < 4; i++)
#pragma unroll
        for (int j = 0; j < 4; j++) acc[i][j] = 0.f;
#pragma unroll
    for (int dd = 0; dd < 64; dd++) {
        float a[4], bv[4];
#pragma unroll
        for (int i = 0; i < 4; i++) a[i] = Qs[dd][ty * 4 + i];
#pragma unroll
        for (int j = 0; j < 4; j++) bv[j] = Ks[dd][tx * 4 + j];
#pragma unroll
        for (int i = 0; i < 4; i++)
#pragma unroll
            for (int j = 0; j < 4; j++) acc[i][j] = fmaf(a[i], bv[j], acc[i][j]);
    }
    float* Ep = g_e + (size_t)bh * SEQ * SEQ;
#pragma unroll
    for (int i = 0; i < 4; i++)
#pragma unroll
        for (int j = 0; j < 4; j++)
            Ep[(size_t)(bm + ty * 4 + i) * SEQ + bn + tx * 4 + j] = acc[i][j] * 0.125f;
}

// ---------------- masked softmax over k ----------------
__global__ void softmax_kernel(const int* __restrict__ src) {
    size_t row = blockIdx.x;              // bh*SEQ + q
    int bh = (int)(row / SEQ);
    int b = bh >> 3;
    float* Ep = g_e + row * SEQ;
    const int* sp = src + b * SEQ;
    int t = threadIdx.x;                  // 128
    __shared__ float red[32];
    float vals[4];
    float mx = -3.0e38f;
#pragma unroll
    for (int i = 0; i < 4; i++) {
        int j = t + i * 128;
        float e = Ep[j];
        if (sp[j] == 0) e = -1e10f;
        vals[i] = e;
        mx = fmaxf(mx, e);
    }
    mx = block_max(mx, red);
    float s = 0.f;
#pragma unroll
    for (int i = 0; i < 4; i++) {
        vals[i] = expf(vals[i] - mx);
        s += vals[i];
    }
    s = block_sum(s, red);
    float inv = 1.f / s;
#pragma unroll
    for (int i = 0; i < 4; i++) Ep[t + i * 128] = vals[i] * inv;
}

// ---------------- o = a @ v (per b,h) ----------------
__global__ void av_kernel() {
    int bh = blockIdx.z;
    int b = bh >> 3, hh = bh & 7;
    int bm = blockIdx.y * 64;
    __shared__ float As[64][65];
    __shared__ float Vs[64][65];
    int tid = threadIdx.x;
    int tx = tid & 15, ty = tid >> 4;
    const float* Ap = g_e + (size_t)bh * SEQ * SEQ;
    const float* Vp = g_v + (size_t)(b * SEQ) * HID + hh * HDIM;
    float acc[4][4];
#pragma unroll
    for (int i = 0; i < 4; i++)
#pragma unroll
        for (int j = 0; j < 4; j++) acc[i][j] = 0.f;

    for (int k0 = 0; k0 < SEQ; k0 += 64) {
#pragma unroll
        for (int i = 0; i < 16; i++) {
            int idx = tid + i * 256;
            int r = idx >> 6, c = idx & 63;
            As[c][r] = Ap[(size_t)(bm + r) * SEQ + k0 + c];   // As[k][m]
            Vs[r][c] = Vp[(size_t)(k0 + r) * HID + c];        // Vs[k][n]
        }
        __syncthreads();
#pragma unroll
        for (int kk = 0; kk < 64; kk++) {
            float a[4], bv[4];
#pragma unroll
            for (int i = 0; i < 4; i++) a[i] = As[kk][ty * 4 + i];
#pragma unroll
            for (int j = 0; j < 4; j++) bv[j] = Vs[kk][tx * 4 + j];
#pragma unroll
            for (int i = 0; i < 4; i++)
#pragma unroll
                for (int j = 0; j < 4; j++) acc[i][j] = fmaf(a[i], bv[j], acc[i][j]);
        }
        __syncthreads();
    }
    float* Op = g_o + (size_t)(b * SEQ) * HID + hh * HDIM;
#pragma unroll
    for (int i = 0; i < 4; i++)
#pragma unroll
        for (int j = 0; j < 4; j++)
            Op[(size_t)(bm + ty * 4 + i) * HID + tx * 4 + j] = acc[i][j];
}

// ---------------- h = LN(h + t) ----------------
__global__ void add_ln_kernel(float* __restrict__ h, const float* __restrict__ t,
                              const float* __restrict__ gvec, const float* __restrict__ bvec) {
    int n = blockIdx.x;
    int d = threadIdx.x;     // 512
    __shared__ float red[32];
    float v = h[(size_t)n * HID + d] + t[(size_t)n * HID + d];
    float mu = block_sum(v, red) * (1.0f / HID);
    float c = v - mu;
    float var = block_sum(c * c, red) * (1.0f / HID);
    h[(size_t)n * HID + d] = c * rsqrtf(var + 1e-5f) * gvec[d] + bvec[d];
}

// ---------------- launcher ----------------
extern "C" void kernel_launch(void* const* d_in, const int* in_sizes, int n_in,
                              void* d_out, int out_size) {
    const int*   src   = (const int*)d_in[0];
    // d_in[1] = src_lengths (unused by reference)
    const int*   nidx  = (const int*)d_in[2];
    const int*   ncnt  = (const int*)d_in[3];
    const float* tint  = (const float*)d_in[4];
    const float* emb   = (const float*)d_in[5];
    const float* timeW = (const float*)d_in[6];
    const float* timeb = (const float*)d_in[7];
    const float* socW  = (const float*)d_in[8];
    const float* socb  = (const float*)d_in[9];
    const float* socg  = (const float*)d_in[10];
    const float* socbe = (const float*)d_in[11];
    const float* projW = (const float*)d_in[12];
    const float* projb = (const float*)d_in[13];
    const float* Wq    = (const float*)d_in[14];
    const float* bq    = (const float*)d_in[15];
    const float* Wk    = (const float*)d_in[16];
    const float* bk    = (const float*)d_in[17];
    const float* Wv    = (const float*)d_in[18];
    const float* bv    = (const float*)d_in[19];
    const float* Wo    = (const float*)d_in[20];
    const float* bo    = (const float*)d_in[21];
    const float* ln1g  = (const float*)d_in[22];
    const float* ln1b  = (const float*)d_in[23];
    const float* ffW1  = (const float*)d_in[24];
    const float* ffb1  = (const float*)d_in[25];
    const float* ffW2  = (const float*)d_in[26];
    const float* ffb2  = (const float*)d_in[27];
    const float* ln2g  = (const float*)d_in[28];
    const float* ln2b  = (const float*)d_in[29];

    float* out = (float*)d_out;

    float *ph, *pq, *pk, *pv, *po, *pt, *pff, *pxs;
    cudaGetSymbolAddress((void**)&ph,  g_h);
    cudaGetSymbolAddress((void**)&pq,  g_q);
    cudaGetSymbolAddress((void**)&pk,  g_k);
    cudaGetSymbolAddress((void**)&pv,  g_v);
    cudaGetSymbolAddress((void**)&po,  g_o);
    cudaGetSymbolAddress((void**)&pt,  g_t);
    cudaGetSymbolAddress((void**)&pff, g_ff);
    cudaGetSymbolAddress((void**)&pxs, g_xs);

    // 1) embed + PE + time
    embed_kernel<<<NTOK, DIMD>>>(src, tint, emb, timeW, timeb);
    // 2) social block -> g_xs
    social_kernel<<<NTOK, DIMD>>>(src, nidx, ncnt, socW, socb, socg, socbe);
    // 3) h = x @ proj_W + proj_b
    sgemm_kernel<<<dim3(HID / 64, NTOK / 64), 256>>>(pxs, projW, projb, ph,
                                                     NTOK, HID, DIMD, 0);

    for (int l = 0; l < NLAYER; l++) {
        const float* Wql = Wq + (size_t)l * HID * HID; const float* bql = bq + l * HID;
        const float* Wkl = Wk + (size_t)l * HID * HID; const float* bkl = bk + l * HID;
        const float* Wvl = Wv + (size_t)l * HID * HID; const float* bvl = bv + l * HID;
        const float* Wol = Wo + (size_t)l * HID * HID; const float* bol = bo + l * HID;

        sgemm_kernel<<<dim3(HID / 64, NTOK / 64), 256>>>(ph, Wql, bql, pq, NTOK, HID, HID, 0);
        sgemm_kernel<<<dim3(HID / 64, NTOK / 64), 256>>>(ph, Wkl, bkl, pk, NTOK, HID, HID, 0);
        sgemm_kernel<<<dim3(HID / 64, NTOK / 64), 256>>>(ph, Wvl, bvl, pv, NTOK, HID, HID, 0);

        score_kernel<<<dim3(SEQ / 64, SEQ / 64, BATCH * NHEAD), 256>>>();
        softmax_kernel<<<BATCH * NHEAD * SEQ, 128>>>(src);
        av_kernel<<<dim3(1, SEQ / 64, BATCH * NHEAD), 256>>>();

        sgemm_kernel<<<dim3(HID / 64, NTOK / 64), 256>>>(po, Wol, bol, pt, NTOK, HID, HID, 0);
        add_ln_kernel<<<NTOK, HID>>>(ph, pt, ln1g + (size_t)l * HID, ln1b + (size_t)l * HID);

        sgemm_kernel<<<dim3(PFF / 64, NTOK / 64), 256>>>(ph, ffW1 + (size_t)l * HID * PFF,
                                                         ffb1 + (size_t)l * PFF, pff,
                                                         NTOK, PFF, HID, 1);
        sgemm_kernel<<<dim3(HID / 64, NTOK / 64), 256>>>(pff, ffW2 + (size_t)l * PFF * HID,
                                                         ffb2 + (size_t)l * HID, pt,
                                                         NTOK, HID, PFF, 0);
        add_ln_kernel<<<NTOK, HID>>>(ph, pt, ln2g + (size_t)l * HID, ln2b + (size_t)l * HID);
    }

    // outputs: h first, then embedded x (post-social)
    cudaMemcpyAsync(out, ph, (size_t)NTOK * HID * sizeof(float),
                    cudaMemcpyDeviceToDevice, 0);
    if (out_size >= NTOK * (HID + DIMD)) {
        cudaMemcpyAsync(out + (size_t)NTOK * HID, pxs,
                        (size_t)NTOK * DIMD * sizeof(float),
                        cudaMemcpyDeviceToDevice, 0);
    }
}

// round 6
// speedup vs baseline: 1.5763x; 1.5763x over previous
#include <cuda_runtime.h>
#include <math.h>

// ---------------- problem dims ----------------
#define NTOK   16384      // B*S
#define DIMD   256        // D
#define HID    512        // H
#define SEQ    512        // S
#define BATCH  32
#define NHEAD  8
#define HDIM   64
#define PFF    2048
#define NLAYER 2
#define NMAXC  15

// ---------------- scratch (static device globals; no allocation) -------------
__device__ float g_x [NTOK * DIMD];            // pre-social embedded x
__device__ float g_xs[NTOK * DIMD];            // post-social x (output #2)
__device__ float g_h [NTOK * HID];
__device__ float g_q [NTOK * HID];
__device__ float g_k [NTOK * HID];
__device__ float g_v [NTOK * HID];
__device__ float g_o [NTOK * HID];
__device__ float g_t [NTOK * HID];
__device__ float g_ff[NTOK * PFF];
__device__ float g_e [(size_t)BATCH * NHEAD * SEQ * SEQ]; // attention scores/probs

// ---------------- reductions ----------------
__device__ __forceinline__ float block_sum(float v, float* red) {
    int lane = threadIdx.x & 31, w = threadIdx.x >> 5;
    int nw = blockDim.x >> 5;
#pragma unroll
    for (int o = 16; o > 0; o >>= 1) v += __shfl_xor_sync(0xffffffffu, v, o);
    if (lane == 0) red[w] = v;
    __syncthreads();
    if (w == 0) {
        float t = (lane < nw) ? red[lane] : 0.f;
#pragma unroll
        for (int o = 16; o > 0; o >>= 1) t += __shfl_xor_sync(0xffffffffu, t, o);
        if (lane == 0) red[0] = t;
    }
    __syncthreads();
    float r = red[0];
    __syncthreads();
    return r;
}

__device__ __forceinline__ float block_max(float v, float* red) {
    int lane = threadIdx.x & 31, w = threadIdx.x >> 5;
    int nw = blockDim.x >> 5;
#pragma unroll
    for (int o = 16; o > 0; o >>= 1) v = fmaxf(v, __shfl_xor_sync(0xffffffffu, v, o));
    if (lane == 0) red[w] = v;
    __syncthreads();
    if (w == 0) {
        float t = (lane < nw) ? red[lane] : -3.0e38f;
#pragma unroll
        for (int o = 16; o > 0; o >>= 1) t = fmaxf(t, __shfl_xor_sync(0xffffffffu, t, o));
        if (lane == 0) red[0] = t;
    }
    __syncthreads();
    float r = red[0];
    __syncthreads();
    return r;
}

// ---------------- 1. embedding + PE + time encoding ----------------
__global__ void embed_kernel(const int* __restrict__ src,
                             const float* __restrict__ tint,
                             const float* __restrict__ emb,
                             const float* __restrict__ timeW,
                             const float* __restrict__ timeb) {
    int n = blockIdx.x;          // token
    int d = threadIdx.x;         // 0..255
    int s = n % SEQ;
    int tok = src[n];
    double div = exp((double)((d >> 1) << 1) * (-9.210340371976184 / 256.0));
    double arg = (double)s * div;
    float pe = (d & 1) ? (float)cos(arg) : (float)sin(arg);
    g_x[n * DIMD + d] = emb[(size_t)tok * DIMD + d] + pe + tint[n] * timeW[d] + timeb[d];
}

// ---------------- 2. neighbor aggregation + social block ----------------
__global__ void social_kernel(const int* __restrict__ src,
                              const int* __restrict__ nidx,
                              const int* __restrict__ ncnt,
                              const float* __restrict__ W,
                              const float* __restrict__ bvec,
                              const float* __restrict__ gvec,
                              const float* __restrict__ beta) {
    int n = blockIdx.x;
    int d = threadIdx.x;         // 0..255
    __shared__ float agg[DIMD];
    __shared__ float red[32];

    int cnt = ncnt[n];
    float xf = g_x[n * DIMD + d];
    float a = 0.f;
    for (int j = 0; j < cnt; j++) {
        int m = nidx[n * NMAXC + j];
        a += g_x[m * DIMD + d];
    }
    a /= (float)(cnt > 0 ? cnt : 1);
    agg[d] = a;
    __syncthreads();

    float z = xf + bvec[d];
#pragma unroll 4
    for (int k = 0; k < DIMD; k++) z = fmaf(agg[k], W[k * DIMD + d], z);

    float mu = block_sum(z, red) * (1.0f / DIMD);
    float c = z - mu;
    float var = block_sum(c * c, red) * (1.0f / DIMD);
    float ln = c * rsqrtf(var + 1e-5f) * gvec[d] + beta[d];
    float soc = fmaxf(ln, 0.f);
    if (cnt <= 0) soc = xf;
    if (src[n] == 0) soc = 0.f;       // PAD token
    g_xs[n * DIMD + d] = xf + 0.2f * soc;
}

// ---------------- SGEMM 128x128 tile, BK=8, 256 thr, 8x8/thread -------------
// C[M,N] = A[M,K] @ B[K,N] + bias (+relu). M%128==0, N%128==0, K%8==0.
__global__ void sgemm128(const float* __restrict__ A,
                         const float* __restrict__ B,
                         const float* __restrict__ bias,
                         float* __restrict__ C,
                         int M, int N, int K, int relu) {
    __shared__ float As[8][132];
    __shared__ float Bs[8][132];
    int tid = threadIdx.x;
    int bm = blockIdx.y * 128, bn = blockIdx.x * 128;
    int tx = tid & 15, ty = tid >> 4;

    int am = tid >> 1, ksub = (tid & 1) * 4;      // A: transpose-load float4 along K
    int kb = tid >> 5, nb4 = (tid & 31) * 4;      // B: direct float4 along N

    const float* Aptr = A + (size_t)(bm + am) * K + ksub;
    const float* Bptr = B + (size_t)kb * N + bn + nb4;

    float acc[8][8];
#pragma unroll
    for (int i = 0; i < 8; i++)
#pragma unroll
        for (int j = 0; j < 8; j++) acc[i][j] = 0.f;

    for (int k0 = 0; k0 < K; k0 += 8) {
        float4 av  = *(const float4*)(Aptr + k0);
        float4 bvv = *(const float4*)(Bptr + (size_t)k0 * N);
        As[ksub + 0][am] = av.x;
        As[ksub + 1][am] = av.y;
        As[ksub + 2][am] = av.z;
        As[ksub + 3][am] = av.w;
        *(float4*)&Bs[kb][nb4] = bvv;
        __syncthreads();
#pragma unroll
        for (int kk = 0; kk < 8; kk++) {
            float a[8], b[8];
            *(float4*)(a)     = *(const float4*)&As[kk][ty * 4];
            *(float4*)(a + 4) = *(const float4*)&As[kk][64 + ty * 4];
            *(float4*)(b)     = *(const float4*)&Bs[kk][tx * 4];
            *(float4*)(b + 4) = *(const float4*)&Bs[kk][64 + tx * 4];
#pragma unroll
            for (int i = 0; i < 8; i++)
#pragma unroll
                for (int j = 0; j < 8; j++) acc[i][j] = fmaf(a[i], b[j], acc[i][j]);
        }
        __syncthreads();
    }

#pragma unroll
    for (int hi = 0; hi < 2; hi++) {
#pragma unroll
        for (int i = 0; i < 4; i++) {
            int m = bm + hi * 64 + ty * 4 + i;
            float* Crow = C + (size_t)m * N;
#pragma unroll
            for (int hj = 0; hj < 2; hj++) {
                int n = bn + hj * 64 + tx * 4;
                float4 bb = *(const float4*)(bias + n);
                float4 v;
                v.x = acc[hi * 4 + i][hj * 4 + 0] + bb.x;
                v.y = acc[hi * 4 + i][hj * 4 + 1] + bb.y;
                v.z = acc[hi * 4 + i][hj * 4 + 2] + bb.z;
                v.w = acc[hi * 4 + i][hj * 4 + 3] + bb.w;
                if (relu) {
                    v.x = fmaxf(v.x, 0.f); v.y = fmaxf(v.y, 0.f);
                    v.z = fmaxf(v.z, 0.f); v.w = fmaxf(v.w, 0.f);
                }
                *(float4*)(Crow + n) = v;
            }
        }
    }
}

// ---------------- scores: e[bh,q,k] = Q.Kt / 8, 128x128 tile, K=64 ----------
__global__ void score128() {
    int bh = blockIdx.z;
    int b = bh >> 3, hh = bh & 7;
    int bm = blockIdx.y * 128, bn = blockIdx.x * 128;
    __shared__ float Qs[8][132];
    __shared__ float Ks[8][132];
    int tid = threadIdx.x;
    int tx = tid & 15, ty = tid >> 4;
    int am = tid >> 1, ksub = (tid & 1) * 4;

    const float* Qp = g_q + (size_t)(b * SEQ + bm + am) * HID + hh * HDIM + ksub;
    const float* Kp = g_k + (size_t)(b * SEQ + bn + am) * HID + hh * HDIM + ksub;

    float acc[8][8];
#pragma unroll
    for (int i = 0; i < 8; i++)
#pragma unroll
        for (int j = 0; j < 8; j++) acc[i][j] = 0.f;

#pragma unroll
    for (int k0 = 0; k0 < HDIM; k0 += 8) {
        float4 qv = *(const float4*)(Qp + k0);
        float4 kv = *(const float4*)(Kp + k0);
        Qs[ksub + 0][am] = qv.x; Qs[ksub + 1][am] = qv.y;
        Qs[ksub + 2][am] = qv.z; Qs[ksub + 3][am] = qv.w;
        Ks[ksub + 0][am] = kv.x; Ks[ksub + 1][am] = kv.y;
        Ks[ksub + 2][am] = kv.z; Ks[ksub + 3][am] = kv.w;
        __syncthreads();
#pragma unroll
        for (int kk = 0; kk < 8; kk++) {
            float a[8], b8[8];
            *(float4*)(a)      = *(const float4*)&Qs[kk][ty * 4];
            *(float4*)(a + 4)  = *(const float4*)&Qs[kk][64 + ty * 4];
            *(float4*)(b8)     = *(const float4*)&Ks[kk][tx * 4];
            *(float4*)(b8 + 4) = *(const float4*)&Ks[kk][64 + tx * 4];
#pragma unroll
            for (int i = 0; i < 8; i++)
#pragma unroll
                for (int j = 0; j < 8; j++) acc[i][j] = fmaf(a[i], b8[j], acc[i][j]);
        }
        __syncthreads();
    }

    float* Ep = g_e + (size_t)bh * SEQ * SEQ;
#pragma unroll
    for (int hi = 0; hi < 2; hi++) {
#pragma unroll
        for (int i = 0; i < 4; i++) {
            int m = bm + hi * 64 + ty * 4 + i;
            float* Erow = Ep + (size_t)m * SEQ;
#pragma unroll
            for (int hj = 0; hj < 2; hj++) {
                int n = bn + hj * 64 + tx * 4;
                float4 v;
                v.x = acc[hi * 4 + i][hj * 4 + 0] * 0.125f;
                v.y = acc[hi * 4 + i][hj * 4 + 1] * 0.125f;
                v.z = acc[hi * 4 + i][hj * 4 + 2] * 0.125f;
                v.w = acc[hi * 4 + i][hj * 4 + 3] * 0.125f;
                *(float4*)(Erow + n) = v;
            }
        }
    }
}

// ---------------- masked softmax over k ----------------
__global__ void softmax_kernel(const int* __restrict__ src) {
    size_t row = blockIdx.x;              // bh*SEQ + q
    int bh = (int)(row / SEQ);
    int b = bh >> 3;
    float* Ep = g_e + row * SEQ;
    const int* sp = src + b * SEQ;
    int t = threadIdx.x;                  // 128
    __shared__ float red[32];
    float vals[4];
    float mx = -3.0e38f;
#pragma unroll
    for (int i = 0; i < 4; i++) {
        int j = t + i * 128;
        float e = Ep[j];
        if (sp[j] == 0) e = -1e10f;
        vals[i] = e;
        mx = fmaxf(mx, e);
    }
    mx = block_max(mx, red);
    float s = 0.f;
#pragma unroll
    for (int i = 0; i < 4; i++) {
        vals[i] = expf(vals[i] - mx);
        s += vals[i];
    }
    s = block_sum(s, red);
    float inv = 1.f / s;
#pragma unroll
    for (int i = 0; i < 4; i++) Ep[t + i * 128] = vals[i] * inv;
}

// ---------------- o = a @ v : 128x64 tile, BK=16, 128 thr, 8x8/thread -------
__global__ void av128() {
    int bh = blockIdx.y;
    int b = bh >> 3, hh = bh & 7;
    int bm = blockIdx.x * 128;
    __shared__ float Aw[16][132];   // a[k][m]
    __shared__ float Vs[16][68];    // v[k][n]
    int tid = threadIdx.x;          // 128
    int tx = tid & 7, ty = tid >> 3;

    const float* Ap = g_e + (size_t)bh * SEQ * SEQ + (size_t)(bm + tid) * SEQ;
    int kb = tid >> 4, nb4 = (tid & 15) * 4;    // V load: 2 float4/thread
    const float* Vp = g_v + (size_t)(b * SEQ) * HID + hh * HDIM;

    float acc[8][8];
#pragma unroll
    for (int i = 0; i < 8; i++)
#pragma unroll
        for (int j = 0; j < 8; j++) acc[i][j] = 0.f;

    for (int k0 = 0; k0 < SEQ; k0 += 16) {
        // A: thread tid owns row (bm+tid), loads 16 consecutive k as 4 float4
#pragma unroll
        for (int q = 0; q < 4; q++) {
            float4 av = *(const float4*)(Ap + k0 + q * 4);
            Aw[q * 4 + 0][tid] = av.x;
            Aw[q * 4 + 1][tid] = av.y;
            Aw[q * 4 + 2][tid] = av.z;
            Aw[q * 4 + 3][tid] = av.w;
        }
        // V tile 16x64: 256 float4 / 128 thr = 2 each
#pragma unroll
        for (int q = 0; q < 2; q++) {
            int kk = kb + q * 8;
            *(float4*)&Vs[kk][nb4] =
                *(const float4*)(Vp + (size_t)(k0 + kk) * HID + nb4);
        }
        __syncthreads();
#pragma unroll
        for (int kk = 0; kk < 16; kk++) {
            float a[8], b8[8];
            *(float4*)(a)      = *(const float4*)&Aw[kk][ty * 4];
            *(float4*)(a + 4)  = *(const float4*)&Aw[kk][64 + ty * 4];
            *(float4*)(b8)     = *(const float4*)&Vs[kk][tx * 4];
            *(float4*)(b8 + 4) = *(const float4*)&Vs[kk][32 + tx * 4];
#pragma unroll
            for (int i = 0; i < 8; i++)
#pragma unroll
                for (int j = 0; j < 8; j++) acc[i][j] = fmaf(a[i], b8[j], acc[i][j]);
        }
        __syncthreads();
    }

    float* Op = g_o + (size_t)(b * SEQ) * HID + hh * HDIM;
#pragma unroll
    for (int hi = 0; hi < 2; hi++) {
#pragma unroll
        for (int i = 0; i < 4; i++) {
            int m = bm + hi * 64 + ty * 4 + i;
            float* Orow = Op + (size_t)m * HID;
#pragma unroll
            for (int hj = 0; hj < 2; hj++) {
                int n = hj * 32 + tx * 4;
                float4 v;
                v.x = acc[hi * 4 + i][hj * 4 + 0];
                v.y = acc[hi * 4 + i][hj * 4 + 1];
                v.z = acc[hi * 4 + i][hj * 4 + 2];
                v.w = acc[hi * 4 + i][hj * 4 + 3];
                *(float4*)(Orow + n) = v;
            }
        }
    }
}

// ---------------- h = LN(h + t) ----------------
__global__ void add_ln_kernel(float* __restrict__ h, const float* __restrict__ t,
                              const float* __restrict__ gvec, const float* __restrict__ bvec) {
    int n = blockIdx.x;
    int d = threadIdx.x;     // 512
    __shared__ float red[32];
    float v = h[(size_t)n * HID + d] + t[(size_t)n * HID + d];
    float mu = block_sum(v, red) * (1.0f / HID);
    float c = v - mu;
    float var = block_sum(c * c, red) * (1.0f / HID);
    h[(size_t)n * HID + d] = c * rsqrtf(var + 1e-5f) * gvec[d] + bvec[d];
}

// ---------------- launcher ----------------
extern "C" void kernel_launch(void* const* d_in, const int* in_sizes, int n_in,
                              void* d_out, int out_size) {
    const int*   src   = (const int*)d_in[0];
    const int*   nidx  = (const int*)d_in[2];
    const int*   ncnt  = (const int*)d_in[3];
    const float* tint  = (const float*)d_in[4];
    const float* emb   = (const float*)d_in[5];
    const float* timeW = (const float*)d_in[6];
    const float* timeb = (const float*)d_in[7];
    const float* socW  = (const float*)d_in[8];
    const float* socb  = (const float*)d_in[9];
    const float* socg  = (const float*)d_in[10];
    const float* socbe = (const float*)d_in[11];
    const float* projW = (const float*)d_in[12];
    const float* projb = (const float*)d_in[13];
    const float* Wq    = (const float*)d_in[14];
    const float* bq    = (const float*)d_in[15];
    const float* Wk    = (const float*)d_in[16];
    const float* bk    = (const float*)d_in[17];
    const float* Wv    = (const float*)d_in[18];
    const float* bv    = (const float*)d_in[19];
    const float* Wo    = (const float*)d_in[20];
    const float* bo    = (const float*)d_in[21];
    const float* ln1g  = (const float*)d_in[22];
    const float* ln1b  = (const float*)d_in[23];
    const float* ffW1  = (const float*)d_in[24];
    const float* ffb1  = (const float*)d_in[25];
    const float* ffW2  = (const float*)d_in[26];
    const float* ffb2  = (const float*)d_in[27];
    const float* ln2g  = (const float*)d_in[28];
    const float* ln2b  = (const float*)d_in[29];

    float* out = (float*)d_out;

    float *ph, *pq, *pk, *pv, *po, *pt, *pff, *pxs;
    cudaGetSymbolAddress((void**)&ph,  g_h);
    cudaGetSymbolAddress((void**)&pq,  g_q);
    cudaGetSymbolAddress((void**)&pk,  g_k);
    cudaGetSymbolAddress((void**)&pv,  g_v);
    cudaGetSymbolAddress((void**)&po,  g_o);
    cudaGetSymbolAddress((void**)&pt,  g_t);
    cudaGetSymbolAddress((void**)&pff, g_ff);
    cudaGetSymbolAddress((void**)&pxs, g_xs);

    embed_kernel<<<NTOK, DIMD>>>(src, tint, emb, timeW, timeb);
    social_kernel<<<NTOK, DIMD>>>(src, nidx, ncnt, socW, socb, socg, socbe);

    sgemm128<<<dim3(HID / 128, NTOK / 128), 256>>>(pxs, projW, projb, ph,
                                                   NTOK, HID, DIMD, 0);

    for (int l = 0; l < NLAYER; l++) {
        const float* Wql = Wq + (size_t)l * HID * HID; const float* bql = bq + l * HID;
        const float* Wkl = Wk + (size_t)l * HID * HID; const float* bkl = bk + l * HID;
        const float* Wvl = Wv + (size_t)l * HID * HID; const float* bvl = bv + l * HID;
        const float* Wol = Wo + (size_t)l * HID * HID; const float* bol = bo + l * HID;

        sgemm128<<<dim3(HID / 128, NTOK / 128), 256>>>(ph, Wql, bql, pq, NTOK, HID, HID, 0);
        sgemm128<<<dim3(HID / 128, NTOK / 128), 256>>>(ph, Wkl, bkl, pk, NTOK, HID, HID, 0);
        sgemm128<<<dim3(HID / 128, NTOK / 128), 256>>>(ph, Wvl, bvl, pv, NTOK, HID, HID, 0);

        score128<<<dim3(SEQ / 128, SEQ / 128, BATCH * NHEAD), 256>>>();
        softmax_kernel<<<BATCH * NHEAD * SEQ, 128>>>(src);
        av128<<<dim3(SEQ / 128, BATCH * NHEAD), 128>>>();

        sgemm128<<<dim3(HID / 128, NTOK / 128), 256>>>(po, Wol, bol, pt, NTOK, HID, HID, 0);
        add_ln_kernel<<<NTOK, HID>>>(ph, pt, ln1g + (size_t)l * HID, ln1b + (size_t)l * HID);

        sgemm128<<<dim3(PFF / 128, NTOK / 128), 256>>>(ph, ffW1 + (size_t)l * HID * PFF,
                                                       ffb1 + (size_t)l * PFF, pff,
                                                       NTOK, PFF, HID, 1);
        sgemm128<<<dim3(HID / 128, NTOK / 128), 256>>>(pff, ffW2 + (size_t)l * PFF * HID,
                                                       ffb2 + (size_t)l * HID, pt,
                                                       NTOK, HID, PFF, 0);
        add_ln_kernel<<<NTOK, HID>>>(ph, pt, ln2g + (size_t)l * HID, ln2b + (size_t)l * HID);
    }

    cudaMemcpyAsync(out, ph, (size_t)NTOK * HID * sizeof(float),
                    cudaMemcpyDeviceToDevice, 0);
    if (out_size >= NTOK * (HID + DIMD)) {
        cudaMemcpyAsync(out + (size_t)NTOK * HID, pxs,
                        (size_t)NTOK * DIMD * sizeof(float),
                        cudaMemcpyDeviceToDevice, 0);
    }
}

// round 9
// speedup vs baseline: 2.5401x; 1.6114x over previous
#include <cuda_runtime.h>
#include <cuda_bf16.h>
#include <math.h>
#include <stdint.h>

// ---------------- problem dims ----------------
#define NTOK   16384      // B*S
#define DIMD   256        // D
#define HID    512        // H
#define SEQ    512        // S
#define BATCH  32
#define NHEAD  8
#define HDIM   64
#define PFF    2048
#define NLAYER 2
#define NMAXC  15

// ---------------- scratch (static device globals; no allocation) -------------
__device__ float g_x [NTOK * DIMD];
__device__ float g_xs[NTOK * DIMD];
__device__ float g_h [NTOK * HID];
__device__ float g_q [NTOK * HID];
__device__ float g_k [NTOK * HID];
__device__ float g_v [NTOK * HID];
__device__ float g_o [NTOK * HID];
__device__ float g_t [NTOK * HID];
__device__ float g_ff[NTOK * PFF];
__device__ float g_e [(size_t)BATCH * NHEAD * SEQ * SEQ];

// ================= helpers =================
__device__ __forceinline__ uint32_t smem_u32(const void* p) {
    uint32_t a;
    asm("{ .reg .u64 t; cvta.to.shared.u64 t, %1; cvt.u32.u64 %0, t; }"
        : "=r"(a) : "l"(p));
    return a;
}
__device__ __forceinline__ uint32_t pack_bf2(float a, float b) {
    __nv_bfloat162 t = __floats2bfloat162_rn(a, b);
    return *reinterpret_cast<uint32_t*>(&t);
}
__device__ __forceinline__ float bf_round(float a) {
    return __bfloat162float(__float2bfloat16(a));
}
// SW64 swizzle for 64-byte rows (conflict-free ldmatrix)
#define SW64(o) ((o) ^ (((o) >> 3) & 0x30))

__device__ __forceinline__ void ldsm4(uint32_t* r, uint32_t addr) {
    asm volatile("ldmatrix.sync.aligned.m8n8.x4.shared.b16 {%0,%1,%2,%3}, [%4];"
                 : "=r"(r[0]), "=r"(r[1]), "=r"(r[2]), "=r"(r[3]) : "r"(addr));
}
__device__ __forceinline__ void ldsm2(uint32_t* r, uint32_t addr) {
    asm volatile("ldmatrix.sync.aligned.m8n8.x2.shared.b16 {%0,%1}, [%2];"
                 : "=r"(r[0]), "=r"(r[1]) : "r"(addr));
}
__device__ __forceinline__ void mma16816(float* c, const uint32_t* a, const uint32_t* b) {
    asm volatile(
        "mma.sync.aligned.m16n8k16.row.col.f32.bf16.bf16.f32 "
        "{%0,%1,%2,%3}, {%4,%5,%6,%7}, {%8,%9}, {%0,%1,%2,%3};"
        : "+f"(c[0]), "+f"(c[1]), "+f"(c[2]), "+f"(c[3])
        : "r"(a[0]), "r"(a[1]), "r"(a[2]), "r"(a[3]), "r"(b[0]), "r"(b[1]));
}

// ================= bf16x3 GEMM on mma.sync =================
// C[M,N] = A[M,K] @ B[K,N] + bias (+relu). M%128==0, N%128==0, K%32==0.
// 128x128 CTA tile, BK=32, 256 threads (8 warps, warp tile 64x32).
// smem per stage (32KB): Ahi[128][32] @0, Alo @8192, Bhi[N=128][K=32] @16384, Blo @24576.
#define MMAG_SMEM (2 * 32768)

__global__ void __launch_bounds__(256, 1)
mma_gemm(const float* __restrict__ A, const float* __restrict__ B,
         const float* __restrict__ bias, float* __restrict__ C,
         int M, int N, int K, int relu) {
    extern __shared__ char smem[];
    uint32_t sb = smem_u32(smem);
    int tid = threadIdx.x, lane = tid & 31, wid = tid >> 5;
    int bm = blockIdx.y * 128, bn = blockIdx.x * 128;
    int wm = (wid >> 2) * 64, wn = (wid & 3) * 32;

    // ---- per-thread producer geometry ----
    // A: 1024 float4 tasks (128 m x 8 k-quads), 4 per thread
    int a_m[4], a_swoff[4];
    const float* a_ptr[4];
#pragma unroll
    for (int p = 0; p < 4; p++) {
        int task = tid + p * 256;
        int m = task >> 3, kq = (task & 7) << 2;
        a_m[p] = m;
        a_swoff[p] = SW64(m * 64 + kq * 2);
        a_ptr[p] = A + (size_t)(bm + m) * K + kq;
    }
    // B: 512 tasks (128 n x 4 k-octets), 2 per thread
    int b_swoff[2];
    const float* b_ptr[2];
#pragma unroll
    for (int g = 0; g < 2; g++) {
        int task = tid + g * 256;
        int n = task & 127, oct = task >> 7;   // oct: g=0 -> 0/1, g=1 -> 2/3
        b_swoff[g] = SW64(n * 64 + oct * 16);
        b_ptr[g] = B + (size_t)(oct * 8) * N + bn + n;
    }

    float acc[4][4][4];
#pragma unroll
    for (int i = 0; i < 4; i++)
#pragma unroll
        for (int j = 0; j < 4; j++)
#pragma unroll
            for (int r = 0; r < 4; r++) acc[i][j][r] = 0.f;

    // ---- fragment smem offsets (constant per thread) ----
    int afo[4], bfo[4];
#pragma unroll
    for (int mb = 0; mb < 4; mb++)
        afo[mb] = (wm + mb * 16 + (lane & 15)) * 64 + ((lane >> 4) & 1) * 16;
#pragma unroll
    for (int nb = 0; nb < 4; nb++)
        bfo[nb] = (wn + nb * 8 + (lane & 7)) * 64 + ((lane >> 3) & 1) * 16;

    const int nch = K >> 5;   // chunks of 32
    // ---- prologue: prefetch chunk 0 ----
    float4 pa[4];
    float pb[16];
#pragma unroll
    for (int p = 0; p < 4; p++) pa[p] = *(const float4*)(a_ptr[p]);
#pragma unroll
    for (int g = 0; g < 2; g++)
#pragma unroll
        for (int i = 0; i < 8; i++) pb[g * 8 + i] = b_ptr[g][(size_t)i * N];

    for (int c = 0; c < nch; c++) {
        uint32_t st = sb + (c & 1) * 32768;
        char* stc = smem + (c & 1) * 32768;

        // ---- convert + store staged regs ----
#pragma unroll
        for (int p = 0; p < 4; p++) {
            float4 v = pa[p];
            float h0 = bf_round(v.x), h1 = bf_round(v.y);
            float h2 = bf_round(v.z), h3 = bf_round(v.w);
            uint2 hi, lo;
            hi.x = pack_bf2(v.x, v.y); hi.y = pack_bf2(v.z, v.w);
            lo.x = pack_bf2(v.x - h0, v.y - h1);
            lo.y = pack_bf2(v.z - h2, v.w - h3);
            *(uint2*)(stc + a_swoff[p])        = hi;
            *(uint2*)(stc + 8192 + a_swoff[p]) = lo;
        }
#pragma unroll
        for (int g = 0; g < 2; g++) {
            float f[8], h[8];
#pragma unroll
            for (int i = 0; i < 8; i++) f[i] = pb[g * 8 + i];
#pragma unroll
            for (int i = 0; i < 8; i++) h[i] = bf_round(f[i]);
            uint4 hi, lo;
            hi.x = pack_bf2(f[0], f[1]); hi.y = pack_bf2(f[2], f[3]);
            hi.z = pack_bf2(f[4], f[5]); hi.w = pack_bf2(f[6], f[7]);
            lo.x = pack_bf2(f[0] - h[0], f[1] - h[1]);
            lo.y = pack_bf2(f[2] - h[2], f[3] - h[3]);
            lo.z = pack_bf2(f[4] - h[4], f[5] - h[5]);
            lo.w = pack_bf2(f[6] - h[6], f[7] - h[7]);
            *(uint4*)(stc + 16384 + b_swoff[g]) = hi;
            *(uint4*)(stc + 24576 + b_swoff[g]) = lo;
        }
        __syncthreads();

        // ---- prefetch next chunk while mma runs ----
        if (c + 1 < nch) {
#pragma unroll
            for (int p = 0; p < 4; p++) {
                a_ptr[p] += 32;
                pa[p] = *(const float4*)(a_ptr[p]);
            }
#pragma unroll
            for (int g = 0; g < 2; g++) {
                b_ptr[g] += (size_t)32 * N;
#pragma unroll
                for (int i = 0; i < 8; i++) pb[g * 8 + i] = b_ptr[g][(size_t)i * N];
            }
        }

        // ---- mma over this chunk: 2 k-steps of 16 ----
#pragma unroll
        for (int ks = 0; ks < 2; ks++) {
            uint32_t Ah[4][4], Al[4][4], Bh[4][2], Bl[4][2];
#pragma unroll
            for (int mb = 0; mb < 4; mb++) {
                uint32_t o = SW64((uint32_t)(afo[mb] + ks * 32));
                ldsm4(Ah[mb], st + o);
                ldsm4(Al[mb], st + 8192 + o);
            }
#pragma unroll
            for (int nb = 0; nb < 4; nb++) {
                uint32_t o = SW64((uint32_t)(bfo[nb] + ks * 32));
                ldsm2(Bh[nb], st + 16384 + o);
                ldsm2(Bl[nb], st + 24576 + o);
            }
#pragma unroll
            for (int mb = 0; mb < 4; mb++)
#pragma unroll
                for (int nb = 0; nb < 4; nb++) {
                    mma16816(acc[mb][nb], Ah[mb], Bh[nb]);
                    mma16816(acc[mb][nb], Ah[mb], Bl[nb]);
                    mma16816(acc[mb][nb], Al[mb], Bh[nb]);
                }
        }
        __syncthreads();
    }

    // ---- epilogue: bias (+relu), direct stores ----
#pragma unroll
    for (int mb = 0; mb < 4; mb++) {
        int m0 = bm + wm + mb * 16 + (lane >> 2);
#pragma unroll
        for (int nb = 0; nb < 4; nb++) {
            int n0 = bn + wn + nb * 8 + (lane & 3) * 2;
            float b0 = bias[n0], b1 = bias[n0 + 1];
            float v0 = acc[mb][nb][0] + b0, v1 = acc[mb][nb][1] + b1;
            float v2 = acc[mb][nb][2] + b0, v3 = acc[mb][nb][3] + b1;
            if (relu) {
                v0 = fmaxf(v0, 0.f); v1 = fmaxf(v1, 0.f);
                v2 = fmaxf(v2, 0.f); v3 = fmaxf(v3, 0.f);
            }
            *(float2*)(C + (size_t)m0 * N + n0)       = make_float2(v0, v1);
            *(float2*)(C + (size_t)(m0 + 8) * N + n0) = make_float2(v2, v3);
        }
    }
}

// ================= reductions =================
__device__ __forceinline__ float block_sum(float v, float* red) {
    int lane = threadIdx.x & 31, w = threadIdx.x >> 5;
    int nw = blockDim.x >> 5;
#pragma unroll
    for (int o = 16; o > 0; o >>= 1) v += __shfl_xor_sync(0xffffffffu, v, o);
    if (lane == 0) red[w] = v;
    __syncthreads();
    if (w == 0) {
        float t = (lane < nw) ? red[lane] : 0.f;
#pragma unroll
        for (int o = 16; o > 0; o >>= 1) t += __shfl_xor_sync(0xffffffffu, t, o);
        if (lane == 0) red[0] = t;
    }
    __syncthreads();
    float r = red[0];
    __syncthreads();
    return r;
}

__device__ __forceinline__ float block_max(float v, float* red) {
    int lane = threadIdx.x & 31, w = threadIdx.x >> 5;
    int nw = blockDim.x >> 5;
#pragma unroll
    for (int o = 16; o > 0; o >>= 1) v = fmaxf(v, __shfl_xor_sync(0xffffffffu, v, o));
    if (lane == 0) red[w] = v;
    __syncthreads();
    if (w == 0) {
        float t = (lane < nw) ? red[lane] : -3.0e38f;
#pragma unroll
        for (int o = 16; o > 0; o >>= 1) t = fmaxf(t, __shfl_xor_sync(0xffffffffu, t, o));
        if (lane == 0) red[0] = t;
    }
    __syncthreads();
    float r = red[0];
    __syncthreads();
    return r;
}

// ================= elementwise / attention kernels =================
__global__ void embed_kernel(const int* __restrict__ src,
                             const float* __restrict__ tint,
                             const float* __restrict__ emb,
                             const float* __restrict__ timeW,
                             const float* __restrict__ timeb) {
    int n = blockIdx.x;
    int d = threadIdx.x;
    int s = n % SEQ;
    int tok = src[n];
    double div = exp((double)((d >> 1) << 1) * (-9.210340371976184 / 256.0));
    double arg = (double)s * div;
    float pe = (d & 1) ? (float)cos(arg) : (float)sin(arg);
    g_x[n * DIMD + d] = emb[(size_t)tok * DIMD + d] + pe + tint[n] * timeW[d] + timeb[d];
}

__global__ void social_kernel(const int* __restrict__ src,
                              const int* __restrict__ nidx,
                              const int* __restrict__ ncnt,
                              const float* __restrict__ W,
                              const float* __restrict__ bvec,
                              const float* __restrict__ gvec,
                              const float* __restrict__ beta) {
    int n = blockIdx.x;
    int d = threadIdx.x;
    __shared__ float agg[DIMD];
    __shared__ float red[32];

    int cnt = ncnt[n];
    float xf = g_x[n * DIMD + d];
    float a = 0.f;
    for (int j = 0; j < cnt; j++) {
        int m = nidx[n * NMAXC + j];
        a += g_x[m * DIMD + d];
    }
    a /= (float)(cnt > 0 ? cnt : 1);
    agg[d] = a;
    __syncthreads();

    float z = xf + bvec[d];
#pragma unroll 4
    for (int k = 0; k < DIMD; k++) z = fmaf(agg[k], W[k * DIMD + d], z);

    float mu = block_sum(z, red) * (1.0f / DIMD);
    float c = z - mu;
    float var = block_sum(c * c, red) * (1.0f / DIMD);
    float ln = c * rsqrtf(var + 1e-5f) * gvec[d] + beta[d];
    float soc = fmaxf(ln, 0.f);
    if (cnt <= 0) soc = xf;
    if (src[n] == 0) soc = 0.f;
    g_xs[n * DIMD + d] = xf + 0.2f * soc;
}

__global__ void score128() {
    int bh = blockIdx.z;
    int b = bh >> 3, hh = bh & 7;
    int bm = blockIdx.y * 128, bn = blockIdx.x * 128;
    __shared__ float Qs[8][132];
    __shared__ float Ks[8][132];
    int tid = threadIdx.x;
    int tx = tid & 15, ty = tid >> 4;
    int am = tid >> 1, ksub = (tid & 1) * 4;

    const float* Qp = g_q + (size_t)(b * SEQ + bm + am) * HID + hh * HDIM + ksub;
    const float* Kp = g_k + (size_t)(b * SEQ + bn + am) * HID + hh * HDIM + ksub;

    float acc[8][8];
#pragma unroll
    for (int i = 0; i < 8; i++)
#pragma unroll
        for (int j = 0; j < 8; j++) acc[i][j] = 0.f;

#pragma unroll
    for (int k0 = 0; k0 < HDIM; k0 += 8) {
        float4 qv = *(const float4*)(Qp + k0);
        float4 kv = *(const float4*)(Kp + k0);
        Qs[ksub + 0][am] = qv.x; Qs[ksub + 1][am] = qv.y;
        Qs[ksub + 2][am] = qv.z; Qs[ksub + 3][am] = qv.w;
        Ks[ksub + 0][am] = kv.x; Ks[ksub + 1][am] = kv.y;
        Ks[ksub + 2][am] = kv.z; Ks[ksub + 3][am] = kv.w;
        __syncthreads();
#pragma unroll
        for (int kk = 0; kk < 8; kk++) {
            float a[8], b8[8];
            *(float4*)(a)      = *(const float4*)&Qs[kk][ty * 4];
            *(float4*)(a + 4)  = *(const float4*)&Qs[kk][64 + ty * 4];
            *(float4*)(b8)     = *(const float4*)&Ks[kk][tx * 4];
            *(float4*)(b8 + 4) = *(const float4*)&Ks[kk][64 + tx * 4];
#pragma unroll
            for (int i = 0; i < 8; i++)
#pragma unroll
                for (int j = 0; j < 8; j++) acc[i][j] = fmaf(a[i], b8[j], acc[i][j]);
        }
        __syncthreads();
    }

    float* Ep = g_e + (size_t)bh * SEQ * SEQ;
#pragma unroll
    for (int hi = 0; hi < 2; hi++) {
#pragma unroll
        for (int i = 0; i < 4; i++) {
            int m = bm + hi * 64 + ty * 4 + i;
            float* Erow = Ep + (size_t)m * SEQ;
#pragma unroll
            for (int hj = 0; hj < 2; hj++) {
                int n = bn + hj * 64 + tx * 4;
                float4 v;
                v.x = acc[hi * 4 + i][hj * 4 + 0] * 0.125f;
                v.y = acc[hi * 4 + i][hj * 4 + 1] * 0.125f;
                v.z = acc[hi * 4 + i][hj * 4 + 2] * 0.125f;
                v.w = acc[hi * 4 + i][hj * 4 + 3] * 0.125f;
                *(float4*)(Erow + n) = v;
            }
        }
    }
}

__global__ void softmax_kernel(const int* __restrict__ src) {
    size_t row = blockIdx.x;
    int bh = (int)(row / SEQ);
    int b = bh >> 3;
    float* Ep = g_e + row * SEQ;
    const int* sp = src + b * SEQ;
    int t = threadIdx.x;
    __shared__ float red[32];
    float vals[4];
    float mx = -3.0e38f;
#pragma unroll
    for (int i = 0; i < 4; i++) {
        int j = t + i * 128;
        float e = Ep[j];
        if (sp[j] == 0) e = -1e10f;
        vals[i] = e;
        mx = fmaxf(mx, e);
    }
    mx = block_max(mx, red);
    float s = 0.f;
#pragma unroll
    for (int i = 0; i < 4; i++) {
        vals[i] = expf(vals[i] - mx);
        s += vals[i];
    }
    s = block_sum(s, red);
    float inv = 1.f / s;
#pragma unroll
    for (int i = 0; i < 4; i++) Ep[t + i * 128] = vals[i] * inv;
}

__global__ void av128() {
    int bh = blockIdx.y;
    int b = bh >> 3, hh = bh & 7;
    int bm = blockIdx.x * 128;
    __shared__ float Aw[16][132];
    __shared__ float Vs[16][68];
    int tid = threadIdx.x;
    int tx = tid & 7, ty = tid >> 3;

    const float* Ap = g_e + (size_t)bh * SEQ * SEQ + (size_t)(bm + tid) * SEQ;
    int kb = tid >> 4, nb4 = (tid & 15) * 4;
    const float* Vp = g_v + (size_t)(b * SEQ) * HID + hh * HDIM;

    float acc[8][8];
#pragma unroll
    for (int i = 0; i < 8; i++)
#pragma unroll
        for (int j = 0; j < 8; j++) acc[i][j] = 0.f;

    for (int k0 = 0; k0 < SEQ; k0 += 16) {
#pragma unroll
        for (int q = 0; q < 4; q++) {
            float4 av = *(const float4*)(Ap + k0 + q * 4);
            Aw[q * 4 + 0][tid] = av.x;
            Aw[q * 4 + 1][tid] = av.y;
            Aw[q * 4 + 2][tid] = av.z;
            Aw[q * 4 + 3][tid] = av.w;
        }
#pragma unroll
        for (int q = 0; q < 2; q++) {
            int kk = kb + q * 8;
            *(float4*)&Vs[kk][nb4] =
                *(const float4*)(Vp + (size_t)(k0 + kk) * HID + nb4);
        }
        __syncthreads();
#pragma unroll
        for (int kk = 0; kk < 16; kk++) {
            float a[8], b8[8];
            *(float4*)(a)      = *(const float4*)&Aw[kk][ty * 4];
            *(float4*)(a + 4)  = *(const float4*)&Aw[kk][64 + ty * 4];
            *(float4*)(b8)     = *(const float4*)&Vs[kk][tx * 4];
            *(float4*)(b8 + 4) = *(const float4*)&Vs[kk][32 + tx * 4];
#pragma unroll
            for (int i = 0; i < 8; i++)
#pragma unroll
                for (int j = 0; j < 8; j++) acc[i][j] = fmaf(a[i], b8[j], acc[i][j]);
        }
        __syncthreads();
    }

    float* Op = g_o + (size_t)(b * SEQ) * HID + hh * HDIM;
#pragma unroll
    for (int hi = 0; hi < 2; hi++) {
#pragma unroll
        for (int i = 0; i < 4; i++) {
            int m = bm + hi * 64 + ty * 4 + i;
            float* Orow = Op + (size_t)m * HID;
#pragma unroll
            for (int hj = 0; hj < 2; hj++) {
                int n = hj * 32 + tx * 4;
                float4 v;
                v.x = acc[hi * 4 + i][hj * 4 + 0];
                v.y = acc[hi * 4 + i][hj * 4 + 1];
                v.z = acc[hi * 4 + i][hj * 4 + 2];
                v.w = acc[hi * 4 + i][hj * 4 + 3];
                *(float4*)(Orow + n) = v;
            }
        }
    }
}

__global__ void add_ln_kernel(float* __restrict__ h, const float* __restrict__ t,
                              const float* __restrict__ gvec, const float* __restrict__ bvec) {
    int n = blockIdx.x;
    int d = threadIdx.x;
    __shared__ float red[32];
    float v = h[(size_t)n * HID + d] + t[(size_t)n * HID + d];
    float mu = block_sum(v, red) * (1.0f / HID);
    float c = v - mu;
    float var = block_sum(c * c, red) * (1.0f / HID);
    h[(size_t)n * HID + d] = c * rsqrtf(var + 1e-5f) * gvec[d] + bvec[d];
}

// ================= launcher =================
extern "C" void kernel_launch(void* const* d_in, const int* in_sizes, int n_in,
                              void* d_out, int out_size) {
    const int*   src   = (const int*)d_in[0];
    const int*   nidx  = (const int*)d_in[2];
    const int*   ncnt  = (const int*)d_in[3];
    const float* tint  = (const float*)d_in[4];
    const float* emb   = (const float*)d_in[5];
    const float* timeW = (const float*)d_in[6];
    const float* timeb = (const float*)d_in[7];
    const float* socW  = (const float*)d_in[8];
    const float* socb  = (const float*)d_in[9];
    const float* socg  = (const float*)d_in[10];
    const float* socbe = (const float*)d_in[11];
    const float* projW = (const float*)d_in[12];
    const float* projb = (const float*)d_in[13];
    const float* Wq    = (const float*)d_in[14];
    const float* bq    = (const float*)d_in[15];
    const float* Wk    = (const float*)d_in[16];
    const float* bk    = (const float*)d_in[17];
    const float* Wv    = (const float*)d_in[18];
    const float* bv    = (const float*)d_in[19];
    const float* Wo    = (const float*)d_in[20];
    const float* bo    = (const float*)d_in[21];
    const float* ln1g  = (const float*)d_in[22];
    const float* ln1b  = (const float*)d_in[23];
    const float* ffW1  = (const float*)d_in[24];
    const float* ffb1  = (const float*)d_in[25];
    const float* ffW2  = (const float*)d_in[26];
    const float* ffb2  = (const float*)d_in[27];
    const float* ln2g  = (const float*)d_in[28];
    const float* ln2b  = (const float*)d_in[29];

    float* out = (float*)d_out;

    float *ph, *pq, *pk, *pv, *po, *pt, *pff, *pxs;
    cudaGetSymbolAddress((void**)&ph,  g_h);
    cudaGetSymbolAddress((void**)&pq,  g_q);
    cudaGetSymbolAddress((void**)&pk,  g_k);
    cudaGetSymbolAddress((void**)&pv,  g_v);
    cudaGetSymbolAddress((void**)&po,  g_o);
    cudaGetSymbolAddress((void**)&pt,  g_t);
    cudaGetSymbolAddress((void**)&pff, g_ff);
    cudaGetSymbolAddress((void**)&pxs, g_xs);

    cudaFuncSetAttribute(mma_gemm, cudaFuncAttributeMaxDynamicSharedMemorySize, MMAG_SMEM);

    embed_kernel<<<NTOK, DIMD>>>(src, tint, emb, timeW, timeb);
    social_kernel<<<NTOK, DIMD>>>(src, nidx, ncnt, socW, socb, socg, socbe);

    mma_gemm<<<dim3(HID / 128, NTOK / 128), 256, MMAG_SMEM>>>(pxs, projW, projb, ph,
                                                              NTOK, HID, DIMD, 0);

    for (int l = 0; l < NLAYER; l++) {
        const float* Wql = Wq + (size_t)l * HID * HID; const float* bql = bq + l * HID;
        const float* Wkl = Wk + (size_t)l * HID * HID; const float* bkl = bk + l * HID;
        const float* Wvl = Wv + (size_t)l * HID * HID; const float* bvl = bv + l * HID;
        const float* Wol = Wo + (size_t)l * HID * HID; const float* bol = bo + l * HID;

        mma_gemm<<<dim3(HID / 128, NTOK / 128), 256, MMAG_SMEM>>>(ph, Wql, bql, pq,
                                                                  NTOK, HID, HID, 0);
        mma_gemm<<<dim3(HID / 128, NTOK / 128), 256, MMAG_SMEM>>>(ph, Wkl, bkl, pk,
                                                                  NTOK, HID, HID, 0);
        mma_gemm<<<dim3(HID / 128, NTOK / 128), 256, MMAG_SMEM>>>(ph, Wvl, bvl, pv,
                                                                  NTOK, HID, HID, 0);

        score128<<<dim3(SEQ / 128, SEQ / 128, BATCH * NHEAD), 256>>>();
        softmax_kernel<<<BATCH * NHEAD * SEQ, 128>>>(src);
        av128<<<dim3(SEQ / 128, BATCH * NHEAD), 128>>>();

        mma_gemm<<<dim3(HID / 128, NTOK / 128), 256, MMAG_SMEM>>>(po, Wol, bol, pt,
                                                                  NTOK, HID, HID, 0);
        add_ln_kernel<<<NTOK, HID>>>(ph, pt, ln1g + (size_t)l * HID, ln1b + (size_t)l * HID);

        mma_gemm<<<dim3(PFF / 128, NTOK / 128), 256, MMAG_SMEM>>>(ph, ffW1 + (size_t)l * HID * PFF,
                                                                  ffb1 + (size_t)l * PFF, pff,
                                                                  NTOK, PFF, HID, 1);
        mma_gemm<<<dim3(HID / 128, NTOK / 128), 256, MMAG_SMEM>>>(pff, ffW2 + (size_t)l * PFF * HID,
                                                                  ffb2 + (size_t)l * HID, pt,
                                                                  NTOK, HID, PFF, 0);
        add_ln_kernel<<<NTOK, HID>>>(ph, pt, ln2g + (size_t)l * HID, ln2b + (size_t)l * HID);
    }

    cudaMemcpyAsync(out, ph, (size_t)NTOK * HID * sizeof(float),
                    cudaMemcpyDeviceToDevice, 0);
    if (out_size >= NTOK * (HID + DIMD)) {
        cudaMemcpyAsync(out + (size_t)NTOK * HID, pxs,
                        (size_t)NTOK * DIMD * sizeof(float),
                        cudaMemcpyDeviceToDevice, 0);
    }
}

// round 11
// speedup vs baseline: 2.7493x; 1.0824x over previous
#include <cuda_runtime.h>
#include <cuda_bf16.h>
#include <math.h>
#include <stdint.h>

// ---------------- problem dims ----------------
#define NTOK   16384      // B*S
#define DIMD   256        // D
#define HID    512        // H
#define SEQ    512        // S
#define BATCH  32
#define NHEAD  8
#define HDIM   64
#define PFF    2048
#define NLAYER 2
#define NMAXC  15

// ---------------- scratch ----------------
__device__ float g_x [NTOK * DIMD];
__device__ float g_xs[NTOK * DIMD];
__device__ float g_h [NTOK * HID];
__device__ float g_q [NTOK * HID];
__device__ float g_k [NTOK * HID];
__device__ float g_v [NTOK * HID];
__device__ float g_o [NTOK * HID];
__device__ float g_t [NTOK * HID];
__device__ float g_ff[NTOK * PFF];
__device__ float g_e [(size_t)BATCH * NHEAD * SEQ * SEQ];

// ================= helpers =================
__device__ __forceinline__ uint32_t smem_u32(const void* p) {
    uint32_t a;
    asm("{ .reg .u64 t; cvta.to.shared.u64 t, %1; cvt.u32.u64 %0, t; }"
        : "=r"(a) : "l"(p));
    return a;
}
__device__ __forceinline__ uint32_t pack_bf2(float a, float b) {
    __nv_bfloat162 t = __floats2bfloat162_rn(a, b);
    return *reinterpret_cast<uint32_t*>(&t);
}
__device__ __forceinline__ float bf_round(float a) {
    return __bfloat162float(__float2bfloat16(a));
}
#define SW64(o)  ((o) ^ (((o) >> 3) & 0x30))
#define SW128(o) ((o) ^ (((o) >> 3) & 0x70))

__device__ __forceinline__ void ldsm4(uint32_t* r, uint32_t addr) {
    asm volatile("ldmatrix.sync.aligned.m8n8.x4.shared.b16 {%0,%1,%2,%3}, [%4];"
                 : "=r"(r[0]), "=r"(r[1]), "=r"(r[2]), "=r"(r[3]) : "r"(addr));
}
__device__ __forceinline__ void ldsm2(uint32_t* r, uint32_t addr) {
    asm volatile("ldmatrix.sync.aligned.m8n8.x2.shared.b16 {%0,%1}, [%2];"
                 : "=r"(r[0]), "=r"(r[1]) : "r"(addr));
}
__device__ __forceinline__ void ldsm2t(uint32_t* r, uint32_t addr) {
    asm volatile("ldmatrix.sync.aligned.m8n8.x2.trans.shared.b16 {%0,%1}, [%2];"
                 : "=r"(r[0]), "=r"(r[1]) : "r"(addr));
}
__device__ __forceinline__ void mma16816(float* c, const uint32_t* a, const uint32_t* b) {
    asm volatile(
        "mma.sync.aligned.m16n8k16.row.col.f32.bf16.bf16.f32 "
        "{%0,%1,%2,%3}, {%4,%5,%6,%7}, {%8,%9}, {%0,%1,%2,%3};"
        : "+f"(c[0]), "+f"(c[1]), "+f"(c[2]), "+f"(c[3])
        : "r"(a[0]), "r"(a[1]), "r"(a[2]), "r"(a[3]), "r"(b[0]), "r"(b[1]));
}

// ================= bf16x3 dense GEMM (unchanged from R8) =================
#define MMAG_SMEM (2 * 32768)

__global__ void __launch_bounds__(256, 1)
mma_gemm(const float* __restrict__ A, const float* __restrict__ B,
         const float* __restrict__ bias, float* __restrict__ C,
         int M, int N, int K, int relu) {
    extern __shared__ char smem[];
    uint32_t sb = smem_u32(smem);
    int tid = threadIdx.x, lane = tid & 31, wid = tid >> 5;
    int bm = blockIdx.y * 128, bn = blockIdx.x * 128;
    int wm = (wid >> 2) * 64, wn = (wid & 3) * 32;

    int a_swoff[4];
    const float* a_ptr[4];
#pragma unroll
    for (int p = 0; p < 4; p++) {
        int task = tid + p * 256;
        int m = task >> 3, kq = (task & 7) << 2;
        a_swoff[p] = SW64(m * 64 + kq * 2);
        a_ptr[p] = A + (size_t)(bm + m) * K + kq;
    }
    int b_swoff[2];
    const float* b_ptr[2];
#pragma unroll
    for (int g = 0; g < 2; g++) {
        int task = tid + g * 256;
        int n = task & 127, oct = task >> 7;
        b_swoff[g] = SW64(n * 64 + oct * 16);
        b_ptr[g] = B + (size_t)(oct * 8) * N + bn + n;
    }

    float acc[4][4][4];
#pragma unroll
    for (int i = 0; i < 4; i++)
#pragma unroll
        for (int j = 0; j < 4; j++)
#pragma unroll
            for (int r = 0; r < 4; r++) acc[i][j][r] = 0.f;

    int afo[4], bfo[4];
#pragma unroll
    for (int mb = 0; mb < 4; mb++)
        afo[mb] = (wm + mb * 16 + (lane & 15)) * 64 + ((lane >> 4) & 1) * 16;
#pragma unroll
    for (int nb = 0; nb < 4; nb++)
        bfo[nb] = (wn + nb * 8 + (lane & 7)) * 64 + ((lane >> 3) & 1) * 16;

    const int nch = K >> 5;
    float4 pa[4];
    float pb[16];
#pragma unroll
    for (int p = 0; p < 4; p++) pa[p] = *(const float4*)(a_ptr[p]);
#pragma unroll
    for (int g = 0; g < 2; g++)
#pragma unroll
        for (int i = 0; i < 8; i++) pb[g * 8 + i] = b_ptr[g][(size_t)i * N];

    for (int c = 0; c < nch; c++) {
        uint32_t st = sb + (c & 1) * 32768;
        char* stc = smem + (c & 1) * 32768;

#pragma unroll
        for (int p = 0; p < 4; p++) {
            float4 v = pa[p];
            float h0 = bf_round(v.x), h1 = bf_round(v.y);
            float h2 = bf_round(v.z), h3 = bf_round(v.w);
            uint2 hi, lo;
            hi.x = pack_bf2(v.x, v.y); hi.y = pack_bf2(v.z, v.w);
            lo.x = pack_bf2(v.x - h0, v.y - h1);
            lo.y = pack_bf2(v.z - h2, v.w - h3);
            *(uint2*)(stc + a_swoff[p])        = hi;
            *(uint2*)(stc + 8192 + a_swoff[p]) = lo;
        }
#pragma unroll
        for (int g = 0; g < 2; g++) {
            float f[8], h[8];
#pragma unroll
            for (int i = 0; i < 8; i++) f[i] = pb[g * 8 + i];
#pragma unroll
            for (int i = 0; i < 8; i++) h[i] = bf_round(f[i]);
            uint4 hi, lo;
            hi.x = pack_bf2(f[0], f[1]); hi.y = pack_bf2(f[2], f[3]);
            hi.z = pack_bf2(f[4], f[5]); hi.w = pack_bf2(f[6], f[7]);
            lo.x = pack_bf2(f[0] - h[0], f[1] - h[1]);
            lo.y = pack_bf2(f[2] - h[2], f[3] - h[3]);
            lo.z = pack_bf2(f[4] - h[4], f[5] - h[5]);
            lo.w = pack_bf2(f[6] - h[6], f[7] - h[7]);
            *(uint4*)(stc + 16384 + b_swoff[g]) = hi;
            *(uint4*)(stc + 24576 + b_swoff[g]) = lo;
        }
        __syncthreads();

        if (c + 1 < nch) {
#pragma unroll
            for (int p = 0; p < 4; p++) {
                a_ptr[p] += 32;
                pa[p] = *(const float4*)(a_ptr[p]);
            }
#pragma unroll
            for (int g = 0; g < 2; g++) {
                b_ptr[g] += (size_t)32 * N;
#pragma unroll
                for (int i = 0; i < 8; i++) pb[g * 8 + i] = b_ptr[g][(size_t)i * N];
            }
        }

#pragma unroll
        for (int ks = 0; ks < 2; ks++) {
            uint32_t Ah[4][4], Al[4][4], Bh[4][2], Bl[4][2];
#pragma unroll
            for (int mb = 0; mb < 4; mb++) {
                uint32_t o = SW64((uint32_t)(afo[mb] + ks * 32));
                ldsm4(Ah[mb], st + o);
                ldsm4(Al[mb], st + 8192 + o);
            }
#pragma unroll
            for (int nb = 0; nb < 4; nb++) {
                uint32_t o = SW64((uint32_t)(bfo[nb] + ks * 32));
                ldsm2(Bh[nb], st + 16384 + o);
                ldsm2(Bl[nb], st + 24576 + o);
            }
#pragma unroll
            for (int mb = 0; mb < 4; mb++)
#pragma unroll
                for (int nb = 0; nb < 4; nb++) {
                    mma16816(acc[mb][nb], Ah[mb], Bh[nb]);
                    mma16816(acc[mb][nb], Ah[mb], Bl[nb]);
                    mma16816(acc[mb][nb], Al[mb], Bh[nb]);
                }
        }
        __syncthreads();
    }

#pragma unroll
    for (int mb = 0; mb < 4; mb++) {
        int m0 = bm + wm + mb * 16 + (lane >> 2);
#pragma unroll
        for (int nb = 0; nb < 4; nb++) {
            int n0 = bn + wn + nb * 8 + (lane & 3) * 2;
            float b0 = bias[n0], b1 = bias[n0 + 1];
            float v0 = acc[mb][nb][0] + b0, v1 = acc[mb][nb][1] + b1;
            float v2 = acc[mb][nb][2] + b0, v3 = acc[mb][nb][3] + b1;
            if (relu) {
                v0 = fmaxf(v0, 0.f); v1 = fmaxf(v1, 0.f);
                v2 = fmaxf(v2, 0.f); v3 = fmaxf(v3, 0.f);
            }
            *(float2*)(C + (size_t)m0 * N + n0)       = make_float2(v0, v1);
            *(float2*)(C + (size_t)(m0 + 8) * N + n0) = make_float2(v2, v3);
        }
    }
}

// ================= mma score: e = Q.K^T / 8 =================
// 128x128 tile per (bh, qtile, ktile). K=64 single stage.
// smem: Qhi@0, Qlo@16384, Khi@32768, Klo@49152 (each 128x64 bf16, SW128 rows)
#define SCORE_SMEM (4 * 16384)

__global__ void __launch_bounds__(256, 1)
mma_score() {
    extern __shared__ char smem[];
    uint32_t sb = smem_u32(smem);
    int tid = threadIdx.x, lane = tid & 31, wid = tid >> 5;
    int bh = blockIdx.z, b = bh >> 3, hh = bh & 7;
    int bm = blockIdx.y * 128, bn = blockIdx.x * 128;
    int wm = (wid >> 2) * 64, wn = (wid & 3) * 32;

    const float* Qp = g_q + (size_t)(b * SEQ) * HID + hh * HDIM;
    const float* Kp = g_k + (size_t)(b * SEQ) * HID + hh * HDIM;

#pragma unroll
    for (int p = 0; p < 8; p++) {
        int task = tid + p * 256;              // 2048 tasks: 128 m x 16 kq
        int m = task >> 4, kq = (task & 15) << 2;
        uint32_t sw = SW128((uint32_t)(m * 128 + kq * 2));
        float4 v = *(const float4*)(Qp + (size_t)(bm + m) * HID + kq);
        {
            float h0 = bf_round(v.x), h1 = bf_round(v.y);
            float h2 = bf_round(v.z), h3 = bf_round(v.w);
            uint2 hi, lo;
            hi.x = pack_bf2(v.x, v.y); hi.y = pack_bf2(v.z, v.w);
            lo.x = pack_bf2(v.x - h0, v.y - h1);
            lo.y = pack_bf2(v.z - h2, v.w - h3);
            *(uint2*)(smem + sw)         = hi;
            *(uint2*)(smem + 16384 + sw) = lo;
        }
        float4 w = *(const float4*)(Kp + (size_t)(bn + m) * HID + kq);
        {
            float h0 = bf_round(w.x), h1 = bf_round(w.y);
            float h2 = bf_round(w.z), h3 = bf_round(w.w);
            uint2 hi, lo;
            hi.x = pack_bf2(w.x, w.y); hi.y = pack_bf2(w.z, w.w);
            lo.x = pack_bf2(w.x - h0, w.y - h1);
            lo.y = pack_bf2(w.z - h2, w.w - h3);
            *(uint2*)(smem + 32768 + sw) = hi;
            *(uint2*)(smem + 49152 + sw) = lo;
        }
    }
    __syncthreads();

    float acc[4][4][4];
#pragma unroll
    for (int i = 0; i < 4; i++)
#pragma unroll
        for (int j = 0; j < 4; j++)
#pragma unroll
            for (int r = 0; r < 4; r++) acc[i][j][r] = 0.f;

    int afo[4], bfo[4];
#pragma unroll
    for (int mb = 0; mb < 4; mb++)
        afo[mb] = (wm + mb * 16 + (lane & 15)) * 128 + ((lane >> 4) & 1) * 16;
#pragma unroll
    for (int nb = 0; nb < 4; nb++)
        bfo[nb] = (wn + nb * 8 + (lane & 7)) * 128 + ((lane >> 3) & 1) * 16;

#pragma unroll
    for (int ks = 0; ks < 4; ks++) {
        uint32_t Ah[4][4], Al[4][4], Bh[4][2], Bl[4][2];
#pragma unroll
        for (int mb = 0; mb < 4; mb++) {
            uint32_t o = SW128((uint32_t)(afo[mb] + ks * 32));
            ldsm4(Ah[mb], sb + o);
            ldsm4(Al[mb], sb + 16384 + o);
        }
#pragma unroll
        for (int nb = 0; nb < 4; nb++) {
            uint32_t o = SW128((uint32_t)(bfo[nb] + ks * 32));
            ldsm2(Bh[nb], sb + 32768 + o);
            ldsm2(Bl[nb], sb + 49152 + o);
        }
#pragma unroll
        for (int mb = 0; mb < 4; mb++)
#pragma unroll
            for (int nb = 0; nb < 4; nb++) {
                mma16816(acc[mb][nb], Ah[mb], Bh[nb]);
                mma16816(acc[mb][nb], Ah[mb], Bl[nb]);
                mma16816(acc[mb][nb], Al[mb], Bh[nb]);
            }
    }

    float* Ep = g_e + (size_t)bh * SEQ * SEQ;
#pragma unroll
    for (int mb = 0; mb < 4; mb++) {
        int m0 = bm + wm + mb * 16 + (lane >> 2);
#pragma unroll
        for (int nb = 0; nb < 4; nb++) {
            int n0 = bn + wn + nb * 8 + (lane & 3) * 2;
            *(float2*)(Ep + (size_t)m0 * SEQ + n0) =
                make_float2(acc[mb][nb][0] * 0.125f, acc[mb][nb][1] * 0.125f);
            *(float2*)(Ep + (size_t)(m0 + 8) * SEQ + n0) =
                make_float2(acc[mb][nb][2] * 0.125f, acc[mb][nb][3] * 0.125f);
        }
    }
}

// ================= mma A@V : o[128q][64hd], K=512, BK=32 double-buffered ====
// stage (24KB): Ahi[128][32]@0, Alo@8192, Vhi[32][64]@16384, Vlo@20480
#define AV_SMEM (2 * 24576)

__global__ void __launch_bounds__(256, 1)
mma_av() {
    extern __shared__ char smem[];
    uint32_t sb = smem_u32(smem);
    int tid = threadIdx.x, lane = tid & 31, wid = tid >> 5;
    int bh = blockIdx.y, b = bh >> 3, hh = bh & 7;
    int bm = blockIdx.x * 128;
    int wm = (wid >> 1) * 32, wn = (wid & 1) * 32;

    const float* Ap = g_e + (size_t)bh * SEQ * SEQ;
    const float* Vp = g_v + (size_t)(b * SEQ) * HID + hh * HDIM;

    // A: 1024 tasks (128 m x 8 kq), 4/thread
    int a_sw[4];
    const float* a_ptr[4];
#pragma unroll
    for (int p = 0; p < 4; p++) {
        int task = tid + p * 256;
        int m = task >> 3, kq = (task & 7) << 2;
        a_sw[p] = SW64(m * 64 + kq * 2);
        a_ptr[p] = Ap + (size_t)(bm + m) * SEQ + kq;
    }
    // V: 512 tasks (32 k x 16 nq), 2/thread
    int v_sw[2];
    const float* v_ptr[2];
#pragma unroll
    for (int g = 0; g < 2; g++) {
        int task = tid + g * 256;
        int k = task >> 4, nq = (task & 15) << 2;
        v_sw[g] = SW128(k * 128 + nq * 2);
        v_ptr[g] = Vp + (size_t)k * HID + nq;
    }

    float acc[2][4][4];
#pragma unroll
    for (int i = 0; i < 2; i++)
#pragma unroll
        for (int j = 0; j < 4; j++)
#pragma unroll
            for (int r = 0; r < 4; r++) acc[i][j][r] = 0.f;

    int afo[2], bco[4];
#pragma unroll
    for (int mb = 0; mb < 2; mb++)
        afo[mb] = (wm + mb * 16 + (lane & 15)) * 64 + ((lane >> 4) & 1) * 16;
#pragma unroll
    for (int nb = 0; nb < 4; nb++)
        bco[nb] = (wn + nb * 8) * 2;           // byte column in V rows

    const int nch = SEQ / 32;                  // 16
    float4 pa[4], pv[2];
#pragma unroll
    for (int p = 0; p < 4; p++) pa[p] = *(const float4*)(a_ptr[p]);
#pragma unroll
    for (int g = 0; g < 2; g++) pv[g] = *(const float4*)(v_ptr[g]);

    for (int c = 0; c < nch; c++) {
        uint32_t st = sb + (c & 1) * 24576;
        char* stc = smem + (c & 1) * 24576;

#pragma unroll
        for (int p = 0; p < 4; p++) {
            float4 v = pa[p];
            float h0 = bf_round(v.x), h1 = bf_round(v.y);
            float h2 = bf_round(v.z), h3 = bf_round(v.w);
            uint2 hi, lo;
            hi.x = pack_bf2(v.x, v.y); hi.y = pack_bf2(v.z, v.w);
            lo.x = pack_bf2(v.x - h0, v.y - h1);
            lo.y = pack_bf2(v.z - h2, v.w - h3);
            *(uint2*)(stc + a_sw[p])        = hi;
            *(uint2*)(stc + 8192 + a_sw[p]) = lo;
        }
#pragma unroll
        for (int g = 0; g < 2; g++) {
            float4 v = pv[g];
            float h0 = bf_round(v.x), h1 = bf_round(v.y);
            float h2 = bf_round(v.z), h3 = bf_round(v.w);
            uint2 hi, lo;
            hi.x = pack_bf2(v.x, v.y); hi.y = pack_bf2(v.z, v.w);
            lo.x = pack_bf2(v.x - h0, v.y - h1);
            lo.y = pack_bf2(v.z - h2, v.w - h3);
            *(uint2*)(stc + 16384 + v_sw[g]) = hi;
            *(uint2*)(stc + 20480 + v_sw[g]) = lo;
        }
        __syncthreads();

        if (c + 1 < nch) {
#pragma unroll
            for (int p = 0; p < 4; p++) {
                a_ptr[p] += 32;
                pa[p] = *(const float4*)(a_ptr[p]);
            }
#pragma unroll
            for (int g = 0; g < 2; g++) {
                v_ptr[g] += (size_t)32 * HID;
                pv[g] = *(const float4*)(v_ptr[g]);
            }
        }

#pragma unroll
        for (int ks = 0; ks < 2; ks++) {
            uint32_t Ah[2][4], Al[2][4], Bh[4][2], Bl[4][2];
#pragma unroll
            for (int mb = 0; mb < 2; mb++) {
                uint32_t o = SW64((uint32_t)(afo[mb] + ks * 32));
                ldsm4(Ah[mb], st + o);
                ldsm4(Al[mb], st + 8192 + o);
            }
#pragma unroll
            for (int nb = 0; nb < 4; nb++) {
                uint32_t o = SW128((uint32_t)((ks * 16 + (lane & 15)) * 128 + bco[nb]));
                ldsm2t(Bh[nb], st + 16384 + o);
                ldsm2t(Bl[nb], st + 20480 + o);
            }
#pragma unroll
            for (int mb = 0; mb < 2; mb++)
#pragma unroll
                for (int nb = 0; nb < 4; nb++) {
                    mma16816(acc[mb][nb], Ah[mb], Bh[nb]);
                    mma16816(acc[mb][nb], Ah[mb], Bl[nb]);
                    mma16816(acc[mb][nb], Al[mb], Bh[nb]);
                }
        }
        __syncthreads();
    }

    float* Op = g_o + (size_t)(b * SEQ) * HID + hh * HDIM;
#pragma unroll
    for (int mb = 0; mb < 2; mb++) {
        int m0 = bm + wm + mb * 16 + (lane >> 2);
#pragma unroll
        for (int nb = 0; nb < 4; nb++) {
            int n0 = wn + nb * 8 + (lane & 3) * 2;
            *(float2*)(Op + (size_t)m0 * HID + n0) =
                make_float2(acc[mb][nb][0], acc[mb][nb][1]);
            *(float2*)(Op + (size_t)(m0 + 8) * HID + n0) =
                make_float2(acc[mb][nb][2], acc[mb][nb][3]);
        }
    }
}

// ================= reductions =================
__device__ __forceinline__ float block_sum(float v, float* red) {
    int lane = threadIdx.x & 31, w = threadIdx.x >> 5;
    int nw = blockDim.x >> 5;
#pragma unroll
    for (int o = 16; o > 0; o >>= 1) v += __shfl_xor_sync(0xffffffffu, v, o);
    if (lane == 0) red[w] = v;
    __syncthreads();
    if (w == 0) {
        float t = (lane < nw) ? red[lane] : 0.f;
#pragma unroll
        for (int o = 16; o > 0; o >>= 1) t += __shfl_xor_sync(0xffffffffu, t, o);
        if (lane == 0) red[0] = t;
    }
    __syncthreads();
    float r = red[0];
    __syncthreads();
    return r;
}

__device__ __forceinline__ float block_max(float v, float* red) {
    int lane = threadIdx.x & 31, w = threadIdx.x >> 5;
    int nw = blockDim.x >> 5;
#pragma unroll
    for (int o = 16; o > 0; o >>= 1) v = fmaxf(v, __shfl_xor_sync(0xffffffffu, v, o));
    if (lane == 0) red[w] = v;
    __syncthreads();
    if (w == 0) {
        float t = (lane < nw) ? red[lane] : -3.0e38f;
#pragma unroll
        for (int o = 16; o > 0; o >>= 1) t = fmaxf(t, __shfl_xor_sync(0xffffffffu, t, o));
        if (lane == 0) red[0] = t;
    }
    __syncthreads();
    float r = red[0];
    __syncthreads();
    return r;
}

// ================= elementwise kernels =================
__global__ void embed_kernel(const int* __restrict__ src,
                             const float* __restrict__ tint,
                             const float* __restrict__ emb,
                             const float* __restrict__ timeW,
                             const float* __restrict__ timeb) {
    int n = blockIdx.x;
    int d = threadIdx.x;
    int s = n % SEQ;
    int tok = src[n];
    double div = exp((double)((d >> 1) << 1) * (-9.210340371976184 / 256.0));
    double arg = (double)s * div;
    float pe = (d & 1) ? (float)cos(arg) : (float)sin(arg);
    g_x[n * DIMD + d] = emb[(size_t)tok * DIMD + d] + pe + tint[n] * timeW[d] + timeb[d];
}

__global__ void social_kernel(const int* __restrict__ src,
                              const int* __restrict__ nidx,
                              const int* __restrict__ ncnt,
                              const float* __restrict__ W,
                              const float* __restrict__ bvec,
                              const float* __restrict__ gvec,
                              const float* __restrict__ beta) {
    int n = blockIdx.x;
    int d = threadIdx.x;
    __shared__ float agg[DIMD];
    __shared__ float red[32];

    int cnt = ncnt[n];
    float xf = g_x[n * DIMD + d];
    float a = 0.f;
    for (int j = 0; j < cnt; j++) {
        int m = nidx[n * NMAXC + j];
        a += g_x[m * DIMD + d];
    }
    a /= (float)(cnt > 0 ? cnt : 1);
    agg[d] = a;
    __syncthreads();

    float z = xf + bvec[d];
#pragma unroll 4
    for (int k = 0; k < DIMD; k++) z = fmaf(agg[k], W[k * DIMD + d], z);

    float mu = block_sum(z, red) * (1.0f / DIMD);
    float c = z - mu;
    float var = block_sum(c * c, red) * (1.0f / DIMD);
    float ln = c * rsqrtf(var + 1e-5f) * gvec[d] + beta[d];
    float soc = fmaxf(ln, 0.f);
    if (cnt <= 0) soc = xf;
    if (src[n] == 0) soc = 0.f;
    g_xs[n * DIMD + d] = xf + 0.2f * soc;
}

__global__ void softmax_kernel(const int* __restrict__ src) {
    size_t row = blockIdx.x;
    int bh = (int)(row / SEQ);
    int b = bh >> 3;
    float* Ep = g_e + row * SEQ;
    const int* sp = src + b * SEQ;
    int t = threadIdx.x;
    __shared__ float red[32];
    float vals[4];
    float mx = -3.0e38f;
#pragma unroll
    for (int i = 0; i < 4; i++) {
        int j = t + i * 128;
        float e = Ep[j];
        if (sp[j] == 0) e = -1e10f;
        vals[i] = e;
        mx = fmaxf(mx, e);
    }
    mx = block_max(mx, red);
    float s = 0.f;
#pragma unroll
    for (int i = 0; i < 4; i++) {
        vals[i] = expf(vals[i] - mx);
        s += vals[i];
    }
    s = block_sum(s, red);
    float inv = 1.f / s;
#pragma unroll
    for (int i = 0; i < 4; i++) Ep[t + i * 128] = vals[i] * inv;
}

__global__ void add_ln_kernel(float* __restrict__ h, const float* __restrict__ t,
                              const float* __restrict__ gvec, const float* __restrict__ bvec) {
    int n = blockIdx.x;
    int d = threadIdx.x;
    __shared__ float red[32];
    float v = h[(size_t)n * HID + d] + t[(size_t)n * HID + d];
    float mu = block_sum(v, red) * (1.0f / HID);
    float c = v - mu;
    float var = block_sum(c * c, red) * (1.0f / HID);
    h[(size_t)n * HID + d] = c * rsqrtf(var + 1e-5f) * gvec[d] + bvec[d];
}

// ================= launcher =================
extern "C" void kernel_launch(void* const* d_in, const int* in_sizes, int n_in,
                              void* d_out, int out_size) {
    const int*   src   = (const int*)d_in[0];
    const int*   nidx  = (const int*)d_in[2];
    const int*   ncnt  = (const int*)d_in[3];
    const float* tint  = (const float*)d_in[4];
    const float* emb   = (const float*)d_in[5];
    const float* timeW = (const float*)d_in[6];
    const float* timeb = (const float*)d_in[7];
    const float* socW  = (const float*)d_in[8];
    const float* socb  = (const float*)d_in[9];
    const float* socg  = (const float*)d_in[10];
    const float* socbe = (const float*)d_in[11];
    const float* projW = (const float*)d_in[12];
    const float* projb = (const float*)d_in[13];
    const float* Wq    = (const float*)d_in[14];
    const float* bq    = (const float*)d_in[15];
    const float* Wk    = (const float*)d_in[16];
    const float* bk    = (const float*)d_in[17];
    const float* Wv    = (const float*)d_in[18];
    const float* bv    = (const float*)d_in[19];
    const float* Wo    = (const float*)d_in[20];
    const float* bo    = (const float*)d_in[21];
    const float* ln1g  = (const float*)d_in[22];
    const float* ln1b  = (const float*)d_in[23];
    const float* ffW1  = (const float*)d_in[24];
    const float* ffb1  = (const float*)d_in[25];
    const float* ffW2  = (const float*)d_in[26];
    const float* ffb2  = (const float*)d_in[27];
    const float* ln2g  = (const float*)d_in[28];
    const float* ln2b  = (const float*)d_in[29];

    float* out = (float*)d_out;

    float *ph, *pq, *pk, *pv, *po, *pt, *pff, *pxs;
    cudaGetSymbolAddress((void**)&ph,  g_h);
    cudaGetSymbolAddress((void**)&pq,  g_q);
    cudaGetSymbolAddress((void**)&pk,  g_k);
    cudaGetSymbolAddress((void**)&pv,  g_v);
    cudaGetSymbolAddress((void**)&po,  g_o);
    cudaGetSymbolAddress((void**)&pt,  g_t);
    cudaGetSymbolAddress((void**)&pff, g_ff);
    cudaGetSymbolAddress((void**)&pxs, g_xs);

    cudaFuncSetAttribute(mma_gemm,  cudaFuncAttributeMaxDynamicSharedMemorySize, MMAG_SMEM);
    cudaFuncSetAttribute(mma_score, cudaFuncAttributeMaxDynamicSharedMemorySize, SCORE_SMEM);
    cudaFuncSetAttribute(mma_av,    cudaFuncAttributeMaxDynamicSharedMemorySize, AV_SMEM);

    embed_kernel<<<NTOK, DIMD>>>(src, tint, emb, timeW, timeb);
    social_kernel<<<NTOK, DIMD>>>(src, nidx, ncnt, socW, socb, socg, socbe);

    mma_gemm<<<dim3(HID / 128, NTOK / 128), 256, MMAG_SMEM>>>(pxs, projW, projb, ph,
                                                              NTOK, HID, DIMD, 0);

    for (int l = 0; l < NLAYER; l++) {
        const float* Wql = Wq + (size_t)l * HID * HID; const float* bql = bq + l * HID;
        const float* Wkl = Wk + (size_t)l * HID * HID; const float* bkl = bk + l * HID;
        const float* Wvl = Wv + (size_t)l * HID * HID; const float* bvl = bv + l * HID;
        const float* Wol = Wo + (size_t)l * HID * HID; const float* bol = bo + l * HID;

        mma_gemm<<<dim3(HID / 128, NTOK / 128), 256, MMAG_SMEM>>>(ph, Wql, bql, pq,
                                                                  NTOK, HID, HID, 0);
        mma_gemm<<<dim3(HID / 128, NTOK / 128), 256, MMAG_SMEM>>>(ph, Wkl, bkl, pk,
                                                                  NTOK, HID, HID, 0);
        mma_gemm<<<dim3(HID / 128, NTOK / 128), 256, MMAG_SMEM>>>(ph, Wvl, bvl, pv,
                                                                  NTOK, HID, HID, 0);

        mma_score<<<dim3(SEQ / 128, SEQ / 128, BATCH * NHEAD), 256, SCORE_SMEM>>>();
        softmax_kernel<<<BATCH * NHEAD * SEQ, 128>>>(src);
        mma_av<<<dim3(SEQ / 128, BATCH * NHEAD), 256, AV_SMEM>>>();

        mma_gemm<<<dim3(HID / 128, NTOK / 128), 256, MMAG_SMEM>>>(po, Wol, bol, pt,
                                                                  NTOK, HID, HID, 0);
        add_ln_kernel<<<NTOK, HID>>>(ph, pt, ln1g + (size_t)l * HID, ln1b + (size_t)l * HID);

        mma_gemm<<<dim3(PFF / 128, NTOK / 128), 256, MMAG_SMEM>>>(ph, ffW1 + (size_t)l * HID * PFF,
                                                                  ffb1 + (size_t)l * PFF, pff,
                                                                  NTOK, PFF, HID, 1);
        mma_gemm<<<dim3(HID / 128, NTOK / 128), 256, MMAG_SMEM>>>(pff, ffW2 + (size_t)l * PFF * HID,
                                                                  ffb2 + (size_t)l * HID, pt,
                                                                  NTOK, HID, PFF, 0);
        add_ln_kernel<<<NTOK, HID>>>(ph, pt, ln2g + (size_t)l * HID, ln2b + (size_t)l * HID);
    }

    cudaMemcpyAsync(out, ph, (size_t)NTOK * HID * sizeof(float),
                    cudaMemcpyDeviceToDevice, 0);
    if (out_size >= NTOK * (HID + DIMD)) {
        cudaMemcpyAsync(out + (size_t)NTOK * HID, pxs,
                        (size_t)NTOK * DIMD * sizeof(float),
                        cudaMemcpyDeviceToDevice, 0);
    }
}

// round 13
// speedup vs baseline: 2.9400x; 1.0694x over previous
#include <cuda_runtime.h>
#include <cuda_bf16.h>
#include <math.h>
#include <stdint.h>

// ---------------- problem dims ----------------
#define NTOK   16384      // B*S
#define DIMD   256        // D
#define HID    512        // H
#define SEQ    512        // S
#define BATCH  32
#define NHEAD  8
#define HDIM   64
#define PFF    2048
#define NLAYER 2
#define NMAXC  15

// ---------------- scratch ----------------
__device__ float g_x [NTOK * DIMD];
__device__ float g_xs[NTOK * DIMD];
__device__ float g_h [NTOK * HID];
__device__ float g_q [NTOK * HID];
__device__ float g_k [NTOK * HID];
__device__ float g_v [NTOK * HID];
__device__ float g_o [NTOK * HID];
__device__ float g_t [NTOK * HID];
__device__ float g_ff[NTOK * PFF];

// ================= helpers =================
__device__ __forceinline__ uint32_t smem_u32(const void* p) {
    uint32_t a;
    asm("{ .reg .u64 t; cvta.to.shared.u64 t, %1; cvt.u32.u64 %0, t; }"
        : "=r"(a) : "l"(p));
    return a;
}
__device__ __forceinline__ uint32_t pack_bf2(float a, float b) {
    __nv_bfloat162 t = __floats2bfloat162_rn(a, b);
    return *reinterpret_cast<uint32_t*>(&t);
}
__device__ __forceinline__ float bf_round(float a) {
    return __bfloat162float(__float2bfloat16(a));
}
#define SW64(o)  ((o) ^ (((o) >> 3) & 0x30))
#define SW128(o) ((o) ^ (((o) >> 3) & 0x70))

__device__ __forceinline__ void ldsm4(uint32_t* r, uint32_t addr) {
    asm volatile("ldmatrix.sync.aligned.m8n8.x4.shared.b16 {%0,%1,%2,%3}, [%4];"
                 : "=r"(r[0]), "=r"(r[1]), "=r"(r[2]), "=r"(r[3]) : "r"(addr));
}
__device__ __forceinline__ void ldsm2(uint32_t* r, uint32_t addr) {
    asm volatile("ldmatrix.sync.aligned.m8n8.x2.shared.b16 {%0,%1}, [%2];"
                 : "=r"(r[0]), "=r"(r[1]) : "r"(addr));
}
__device__ __forceinline__ void ldsm2t(uint32_t* r, uint32_t addr) {
    asm volatile("ldmatrix.sync.aligned.m8n8.x2.trans.shared.b16 {%0,%1}, [%2];"
                 : "=r"(r[0]), "=r"(r[1]) : "r"(addr));
}
__device__ __forceinline__ void mma16816(float* c, const uint32_t* a, const uint32_t* b) {
    asm volatile(
        "mma.sync.aligned.m16n8k16.row.col.f32.bf16.bf16.f32 "
        "{%0,%1,%2,%3}, {%4,%5,%6,%7}, {%8,%9}, {%0,%1,%2,%3};"
        : "+f"(c[0]), "+f"(c[1]), "+f"(c[2]), "+f"(c[3])
        : "r"(a[0]), "r"(a[1]), "r"(a[2]), "r"(a[3]), "r"(b[0]), "r"(b[1]));
}

// ================= bf16x3 dense GEMM (unchanged) =================
#define MMAG_SMEM (2 * 32768)

__global__ void __launch_bounds__(256, 1)
mma_gemm(const float* __restrict__ A, const float* __restrict__ B,
         const float* __restrict__ bias, float* __restrict__ C,
         int M, int N, int K, int relu) {
    extern __shared__ char smem[];
    uint32_t sb = smem_u32(smem);
    int tid = threadIdx.x, lane = tid & 31, wid = tid >> 5;
    int bm = blockIdx.y * 128, bn = blockIdx.x * 128;
    int wm = (wid >> 2) * 64, wn = (wid & 3) * 32;

    int a_swoff[4];
    const float* a_ptr[4];
#pragma unroll
    for (int p = 0; p < 4; p++) {
        int task = tid + p * 256;
        int m = task >> 3, kq = (task & 7) << 2;
        a_swoff[p] = SW64(m * 64 + kq * 2);
        a_ptr[p] = A + (size_t)(bm + m) * K + kq;
    }
    int b_swoff[2];
    const float* b_ptr[2];
#pragma unroll
    for (int g = 0; g < 2; g++) {
        int task = tid + g * 256;
        int n = task & 127, oct = task >> 7;
        b_swoff[g] = SW64(n * 64 + oct * 16);
        b_ptr[g] = B + (size_t)(oct * 8) * N + bn + n;
    }

    float acc[4][4][4];
#pragma unroll
    for (int i = 0; i < 4; i++)
#pragma unroll
        for (int j = 0; j < 4; j++)
#pragma unroll
            for (int r = 0; r < 4; r++) acc[i][j][r] = 0.f;

    int afo[4], bfo[4];
#pragma unroll
    for (int mb = 0; mb < 4; mb++)
        afo[mb] = (wm + mb * 16 + (lane & 15)) * 64 + ((lane >> 4) & 1) * 16;
#pragma unroll
    for (int nb = 0; nb < 4; nb++)
        bfo[nb] = (wn + nb * 8 + (lane & 7)) * 64 + ((lane >> 3) & 1) * 16;

    const int nch = K >> 5;
    float4 pa[4];
    float pb[16];
#pragma unroll
    for (int p = 0; p < 4; p++) pa[p] = *(const float4*)(a_ptr[p]);
#pragma unroll
    for (int g = 0; g < 2; g++)
#pragma unroll
        for (int i = 0; i < 8; i++) pb[g * 8 + i] = b_ptr[g][(size_t)i * N];

    for (int c = 0; c < nch; c++) {
        uint32_t st = sb + (c & 1) * 32768;
        char* stc = smem + (c & 1) * 32768;

#pragma unroll
        for (int p = 0; p < 4; p++) {
            float4 v = pa[p];
            float h0 = bf_round(v.x), h1 = bf_round(v.y);
            float h2 = bf_round(v.z), h3 = bf_round(v.w);
            uint2 hi, lo;
            hi.x = pack_bf2(v.x, v.y); hi.y = pack_bf2(v.z, v.w);
            lo.x = pack_bf2(v.x - h0, v.y - h1);
            lo.y = pack_bf2(v.z - h2, v.w - h3);
            *(uint2*)(stc + a_swoff[p])        = hi;
            *(uint2*)(stc + 8192 + a_swoff[p]) = lo;
        }
#pragma unroll
        for (int g = 0; g < 2; g++) {
            float f[8], h[8];
#pragma unroll
            for (int i = 0; i < 8; i++) f[i] = pb[g * 8 + i];
#pragma unroll
            for (int i = 0; i < 8; i++) h[i] = bf_round(f[i]);
            uint4 hi, lo;
            hi.x = pack_bf2(f[0], f[1]); hi.y = pack_bf2(f[2], f[3]);
            hi.z = pack_bf2(f[4], f[5]); hi.w = pack_bf2(f[6], f[7]);
            lo.x = pack_bf2(f[0] - h[0], f[1] - h[1]);
            lo.y = pack_bf2(f[2] - h[2], f[3] - h[3]);
            lo.z = pack_bf2(f[4] - h[4], f[5] - h[5]);
            lo.w = pack_bf2(f[6] - h[6], f[7] - h[7]);
            *(uint4*)(stc + 16384 + b_swoff[g]) = hi;
            *(uint4*)(stc + 24576 + b_swoff[g]) = lo;
        }
        __syncthreads();

        if (c + 1 < nch) {
#pragma unroll
            for (int p = 0; p < 4; p++) {
                a_ptr[p] += 32;
                pa[p] = *(const float4*)(a_ptr[p]);
            }
#pragma unroll
            for (int g = 0; g < 2; g++) {
                b_ptr[g] += (size_t)32 * N;
#pragma unroll
                for (int i = 0; i < 8; i++) pb[g * 8 + i] = b_ptr[g][(size_t)i * N];
            }
        }

#pragma unroll
        for (int ks = 0; ks < 2; ks++) {
            uint32_t Ah[4][4], Al[4][4], Bh[4][2], Bl[4][2];
#pragma unroll
            for (int mb = 0; mb < 4; mb++) {
                uint32_t o = SW64((uint32_t)(afo[mb] + ks * 32));
                ldsm4(Ah[mb], st + o);
                ldsm4(Al[mb], st + 8192 + o);
            }
#pragma unroll
            for (int nb = 0; nb < 4; nb++) {
                uint32_t o = SW64((uint32_t)(bfo[nb] + ks * 32));
                ldsm2(Bh[nb], st + 16384 + o);
                ldsm2(Bl[nb], st + 24576 + o);
            }
#pragma unroll
            for (int mb = 0; mb < 4; mb++)
#pragma unroll
                for (int nb = 0; nb < 4; nb++) {
                    mma16816(acc[mb][nb], Ah[mb], Bh[nb]);
                    mma16816(acc[mb][nb], Ah[mb], Bl[nb]);
                    mma16816(acc[mb][nb], Al[mb], Bh[nb]);
                }
        }
        __syncthreads();
    }

#pragma unroll
    for (int mb = 0; mb < 4; mb++) {
        int m0 = bm + wm + mb * 16 + (lane >> 2);
#pragma unroll
        for (int nb = 0; nb < 4; nb++) {
            int n0 = bn + wn + nb * 8 + (lane & 3) * 2;
            float b0 = bias[n0], b1 = bias[n0 + 1];
            float v0 = acc[mb][nb][0] + b0, v1 = acc[mb][nb][1] + b1;
            float v2 = acc[mb][nb][2] + b0, v3 = acc[mb][nb][3] + b1;
            if (relu) {
                v0 = fmaxf(v0, 0.f); v1 = fmaxf(v1, 0.f);
                v2 = fmaxf(v2, 0.f); v3 = fmaxf(v3, 0.f);
            }
            *(float2*)(C + (size_t)m0 * N + n0)       = make_float2(v0, v1);
            *(float2*)(C + (size_t)(m0 + 8) * N + n0) = make_float2(v2, v3);
        }
    }
}

// ================= flash attention =================
// Grid (SEQ/128, BATCH*NHEAD). 256 threads, 8 warps x 16 q-rows.
// smem: Qhi@0 Qlo@16384 Khi@32768 Klo@49152 Vhi@65536 Vlo@81920 mask@98304
#define FL_SMEM (98304 + SEQ * 4)

__global__ void __launch_bounds__(256, 1)
flash_attn(const int* __restrict__ src) {
    extern __shared__ char smem[];
    uint32_t sb = smem_u32(smem);
    int tid = threadIdx.x, lane = tid & 31, wid = tid >> 5;
    int bh = blockIdx.y, b = bh >> 3, hh = bh & 7;
    int bm = blockIdx.x * 128;
    int wq = wid * 16;

    const float* Qp = g_q + (size_t)(b * SEQ) * HID + hh * HDIM;
    const float* Kp = g_k + (size_t)(b * SEQ) * HID + hh * HDIM;
    const float* Vp = g_v + (size_t)(b * SEQ) * HID + hh * HDIM;
    float* maskp = (float*)(smem + 98304);

    // key mask for whole sequence (1.0 = PAD/masked)
    for (int i = tid; i < SEQ; i += 256)
        maskp[i] = (src[b * SEQ + i] == 0) ? 1.f : 0.f;

    // ---- Q tile 128x64, hi/lo, SW128 rows ----
#pragma unroll
    for (int p = 0; p < 8; p++) {
        int task = tid + p * 256;
        int m = task >> 4, kq = (task & 15) << 2;
        float4 v = *(const float4*)(Qp + (size_t)(bm + m) * HID + kq);
        float h0 = bf_round(v.x), h1 = bf_round(v.y);
        float h2 = bf_round(v.z), h3 = bf_round(v.w);
        uint2 hi, lo;
        hi.x = pack_bf2(v.x, v.y); hi.y = pack_bf2(v.z, v.w);
        lo.x = pack_bf2(v.x - h0, v.y - h1);
        lo.y = pack_bf2(v.z - h2, v.w - h3);
        uint32_t sw = SW128((uint32_t)(m * 128 + kq * 2));
        *(uint2*)(smem + sw)         = hi;
        *(uint2*)(smem + 16384 + sw) = lo;
    }
    __syncthreads();

    // ---- Q fragments (held for the whole kernel) ----
    uint32_t qh[4][4], ql[4][4];
    {
        int aro = (wq + (lane & 15)) * 128 + ((lane >> 4) & 1) * 16;
#pragma unroll
        for (int ks = 0; ks < 4; ks++) {
            uint32_t o = SW128((uint32_t)(aro + ks * 32));
            ldsm4(qh[ks], sb + o);
            ldsm4(ql[ks], sb + 16384 + o);
        }
    }

    float oacc[8][4];
#pragma unroll
    for (int i = 0; i < 8; i++)
#pragma unroll
        for (int r = 0; r < 4; r++) oacc[i][r] = 0.f;
    float m0 = -3.0e38f, m1 = -3.0e38f, l0 = 0.f, l1 = 0.f;

    for (int it = 0; it < SEQ / 128; it++) {
        int k0 = it * 128;
        // ---- load K,V tiles (128x64 each, hi/lo) ----
#pragma unroll
        for (int p = 0; p < 8; p++) {
            int task = tid + p * 256;
            int r = task >> 4, kq = (task & 15) << 2;
            uint32_t sw = SW128((uint32_t)(r * 128 + kq * 2));
            float4 v = *(const float4*)(Kp + (size_t)(k0 + r) * HID + kq);
            {
                float h0f = bf_round(v.x), h1f = bf_round(v.y);
                float h2f = bf_round(v.z), h3f = bf_round(v.w);
                uint2 hi, lo;
                hi.x = pack_bf2(v.x, v.y); hi.y = pack_bf2(v.z, v.w);
                lo.x = pack_bf2(v.x - h0f, v.y - h1f);
                lo.y = pack_bf2(v.z - h2f, v.w - h3f);
                *(uint2*)(smem + 32768 + sw) = hi;
                *(uint2*)(smem + 49152 + sw) = lo;
            }
            float4 w = *(const float4*)(Vp + (size_t)(k0 + r) * HID + kq);
            {
                float h0f = bf_round(w.x), h1f = bf_round(w.y);
                float h2f = bf_round(w.z), h3f = bf_round(w.w);
                uint2 hi, lo;
                hi.x = pack_bf2(w.x, w.y); hi.y = pack_bf2(w.z, w.w);
                lo.x = pack_bf2(w.x - h0f, w.y - h1f);
                lo.y = pack_bf2(w.z - h2f, w.w - h3f);
                *(uint2*)(smem + 65536 + sw) = hi;
                *(uint2*)(smem + 81920 + sw) = lo;
            }
        }
        __syncthreads();

        // ---- S = Q.K^T (16 q-rows x 128 keys per warp) ----
        float sc[16][4];
#pragma unroll
        for (int nb = 0; nb < 16; nb++)
#pragma unroll
            for (int r = 0; r < 4; r++) sc[nb][r] = 0.f;

#pragma unroll
        for (int ks = 0; ks < 4; ks++) {
#pragma unroll
            for (int nb = 0; nb < 16; nb++) {
                uint32_t o = SW128((uint32_t)((nb * 8 + (lane & 7)) * 128 +
                                              ((lane >> 3) & 1) * 16 + ks * 32));
                uint32_t Kh[2], Kl[2];
                ldsm2(Kh, sb + 32768 + o);
                ldsm2(Kl, sb + 49152 + o);
                mma16816(sc[nb], qh[ks], Kh);
                mma16816(sc[nb], qh[ks], Kl);
                mma16816(sc[nb], ql[ks], Kh);
            }
        }

        // ---- mask + scale + row max ----
        float mx0 = -3.0e38f, mx1 = -3.0e38f;
#pragma unroll
        for (int nb = 0; nb < 16; nb++) {
            int c = k0 + nb * 8 + (lane & 3) * 2;
            float f0 = maskp[c], f1 = maskp[c + 1];
            sc[nb][0] = (f0 != 0.f) ? -1e10f : sc[nb][0] * 0.125f;
            sc[nb][1] = (f1 != 0.f) ? -1e10f : sc[nb][1] * 0.125f;
            sc[nb][2] = (f0 != 0.f) ? -1e10f : sc[nb][2] * 0.125f;
            sc[nb][3] = (f1 != 0.f) ? -1e10f : sc[nb][3] * 0.125f;
            mx0 = fmaxf(mx0, fmaxf(sc[nb][0], sc[nb][1]));
            mx1 = fmaxf(mx1, fmaxf(sc[nb][2], sc[nb][3]));
        }
        mx0 = fmaxf(mx0, __shfl_xor_sync(0xffffffffu, mx0, 1));
        mx0 = fmaxf(mx0, __shfl_xor_sync(0xffffffffu, mx0, 2));
        mx1 = fmaxf(mx1, __shfl_xor_sync(0xffffffffu, mx1, 1));
        mx1 = fmaxf(mx1, __shfl_xor_sync(0xffffffffu, mx1, 2));

        float mn0 = fmaxf(m0, mx0), mn1 = fmaxf(m1, mx1);
        float cor0 = expf(m0 - mn0), cor1 = expf(m1 - mn1);
        m0 = mn0; m1 = mn1;

        // ---- P = exp(S - m), row sums ----
        float rs0 = 0.f, rs1 = 0.f;
#pragma unroll
        for (int nb = 0; nb < 16; nb++) {
            sc[nb][0] = expf(sc[nb][0] - mn0);
            sc[nb][1] = expf(sc[nb][1] - mn0);
            sc[nb][2] = expf(sc[nb][2] - mn1);
            sc[nb][3] = expf(sc[nb][3] - mn1);
            rs0 += sc[nb][0] + sc[nb][1];
            rs1 += sc[nb][2] + sc[nb][3];
        }
        rs0 += __shfl_xor_sync(0xffffffffu, rs0, 1);
        rs0 += __shfl_xor_sync(0xffffffffu, rs0, 2);
        rs1 += __shfl_xor_sync(0xffffffffu, rs1, 1);
        rs1 += __shfl_xor_sync(0xffffffffu, rs1, 2);
        l0 = l0 * cor0 + rs0;
        l1 = l1 * cor1 + rs1;

#pragma unroll
        for (int ob = 0; ob < 8; ob++) {
            oacc[ob][0] *= cor0; oacc[ob][1] *= cor0;
            oacc[ob][2] *= cor1; oacc[ob][3] *= cor1;
        }

        // ---- O += P.V (register repack C->A, 3-term) ----
#pragma unroll
        for (int kv = 0; kv < 8; kv++) {
            float p00 = sc[2 * kv][0],     p01 = sc[2 * kv][1];
            float p10 = sc[2 * kv][2],     p11 = sc[2 * kv][3];
            float r00 = sc[2 * kv + 1][0], r01 = sc[2 * kv + 1][1];
            float r10 = sc[2 * kv + 1][2], r11 = sc[2 * kv + 1][3];
            uint32_t Ah[4], Al[4];
            Ah[0] = pack_bf2(p00, p01);
            Ah[1] = pack_bf2(p10, p11);
            Ah[2] = pack_bf2(r00, r01);
            Ah[3] = pack_bf2(r10, r11);
            Al[0] = pack_bf2(p00 - bf_round(p00), p01 - bf_round(p01));
            Al[1] = pack_bf2(p10 - bf_round(p10), p11 - bf_round(p11));
            Al[2] = pack_bf2(r00 - bf_round(r00), r01 - bf_round(r01));
            Al[3] = pack_bf2(r10 - bf_round(r10), r11 - bf_round(r11));
#pragma unroll
            for (int nb = 0; nb < 8; nb++) {
                uint32_t o = SW128((uint32_t)((kv * 16 + (lane & 15)) * 128 + nb * 16));
                uint32_t Vh[2], Vl[2];
                ldsm2t(Vh, sb + 65536 + o);
                ldsm2t(Vl, sb + 81920 + o);
                mma16816(oacc[nb], Ah, Vh);
                mma16816(oacc[nb], Ah, Vl);
                mma16816(oacc[nb], Al, Vh);
            }
        }
        __syncthreads();
    }

    // ---- epilogue: O / l ----
    float inv0 = 1.f / l0, inv1 = 1.f / l1;
    int r0 = bm + wq + (lane >> 2);
    float* Op = g_o + (size_t)(b * SEQ + r0) * HID + hh * HDIM;
#pragma unroll
    for (int nb = 0; nb < 8; nb++) {
        int c = nb * 8 + (lane & 3) * 2;
        *(float2*)(Op + c) = make_float2(oacc[nb][0] * inv0, oacc[nb][1] * inv0);
        *(float2*)(Op + (size_t)8 * HID + c) =
            make_float2(oacc[nb][2] * inv1, oacc[nb][3] * inv1);
    }
}

// ================= reductions =================
__device__ __forceinline__ float block_sum(float v, float* red) {
    int lane = threadIdx.x & 31, w = threadIdx.x >> 5;
    int nw = blockDim.x >> 5;
#pragma unroll
    for (int o = 16; o > 0; o >>= 1) v += __shfl_xor_sync(0xffffffffu, v, o);
    if (lane == 0) red[w] = v;
    __syncthreads();
    if (w == 0) {
        float t = (lane < nw) ? red[lane] : 0.f;
#pragma unroll
        for (int o = 16; o > 0; o >>= 1) t += __shfl_xor_sync(0xffffffffu, t, o);
        if (lane == 0) red[0] = t;
    }
    __syncthreads();
    float r = red[0];
    __syncthreads();
    return r;
}

// ================= elementwise kernels =================
__global__ void embed_kernel(const int* __restrict__ src,
                             const float* __restrict__ tint,
                             const float* __restrict__ emb,
                             const float* __restrict__ timeW,
                             const float* __restrict__ timeb) {
    int n = blockIdx.x;
    int d = threadIdx.x;
    int s = n % SEQ;
    int tok = src[n];
    double div = exp((double)((d >> 1) << 1) * (-9.210340371976184 / 256.0));
    double arg = (double)s * div;
    float pe = (d & 1) ? (float)cos(arg) : (float)sin(arg);
    g_x[n * DIMD + d] = emb[(size_t)tok * DIMD + d] + pe + tint[n] * timeW[d] + timeb[d];
}

__global__ void social_kernel(const int* __restrict__ src,
                              const int* __restrict__ nidx,
                              const int* __restrict__ ncnt,
                              const float* __restrict__ W,
                              const float* __restrict__ bvec,
                              const float* __restrict__ gvec,
                              const float* __restrict__ beta) {
    int n = blockIdx.x;
    int d = threadIdx.x;
    __shared__ float agg[DIMD];
    __shared__ float red[32];

    int cnt = ncnt[n];
    float xf = g_x[n * DIMD + d];
    float a = 0.f;
    for (int j = 0; j < cnt; j++) {
        int m = nidx[n * NMAXC + j];
        a += g_x[m * DIMD + d];
    }
    a /= (float)(cnt > 0 ? cnt : 1);
    agg[d] = a;
    __syncthreads();

    float z = xf + bvec[d];
#pragma unroll 4
    for (int k = 0; k < DIMD; k++) z = fmaf(agg[k], W[k * DIMD + d], z);

    float mu = block_sum(z, red) * (1.0f / DIMD);
    float c = z - mu;
    float var = block_sum(c * c, red) * (1.0f / DIMD);
    float ln = c * rsqrtf(var + 1e-5f) * gvec[d] + beta[d];
    float soc = fmaxf(ln, 0.f);
    if (cnt <= 0) soc = xf;
    if (src[n] == 0) soc = 0.f;
    g_xs[n * DIMD + d] = xf + 0.2f * soc;
}

__global__ void add_ln_kernel(float* __restrict__ h, const float* __restrict__ t,
                              const float* __restrict__ gvec, const float* __restrict__ bvec) {
    int n = blockIdx.x;
    int d = threadIdx.x;
    __shared__ float red[32];
    float v = h[(size_t)n * HID + d] + t[(size_t)n * HID + d];
    float mu = block_sum(v, red) * (1.0f / HID);
    float c = v - mu;
    float var = block_sum(c * c, red) * (1.0f / HID);
    h[(size_t)n * HID + d] = c * rsqrtf(var + 1e-5f) * gvec[d] + bvec[d];
}

// ================= launcher =================
extern "C" void kernel_launch(void* const* d_in, const int* in_sizes, int n_in,
                              void* d_out, int out_size) {
    const int*   src   = (const int*)d_in[0];
    const int*   nidx  = (const int*)d_in[2];
    const int*   ncnt  = (const int*)d_in[3];
    const float* tint  = (const float*)d_in[4];
    const float* emb   = (const float*)d_in[5];
    const float* timeW = (const float*)d_in[6];
    const float* timeb = (const float*)d_in[7];
    const float* socW  = (const float*)d_in[8];
    const float* socb  = (const float*)d_in[9];
    const float* socg  = (const float*)d_in[10];
    const float* socbe = (const float*)d_in[11];
    const float* projW = (const float*)d_in[12];
    const float* projb = (const float*)d_in[13];
    const float* Wq    = (const float*)d_in[14];
    const float* bq    = (const float*)d_in[15];
    const float* Wk    = (const float*)d_in[16];
    const float* bk    = (const float*)d_in[17];
    const float* Wv    = (const float*)d_in[18];
    const float* bv    = (const float*)d_in[19];
    const float* Wo    = (const float*)d_in[20];
    const float* bo    = (const float*)d_in[21];
    const float* ln1g  = (const float*)d_in[22];
    const float* ln1b  = (const float*)d_in[23];
    const float* ffW1  = (const float*)d_in[24];
    const float* ffb1  = (const float*)d_in[25];
    const float* ffW2  = (const float*)d_in[26];
    const float* ffb2  = (const float*)d_in[27];
    const float* ln2g  = (const float*)d_in[28];
    const float* ln2b  = (const float*)d_in[29];

    float* out = (float*)d_out;

    float *ph, *pq, *pk, *pv, *po, *pt, *pff, *pxs;
    cudaGetSymbolAddress((void**)&ph,  g_h);
    cudaGetSymbolAddress((void**)&pq,  g_q);
    cudaGetSymbolAddress((void**)&pk,  g_k);
    cudaGetSymbolAddress((void**)&pv,  g_v);
    cudaGetSymbolAddress((void**)&po,  g_o);
    cudaGetSymbolAddress((void**)&pt,  g_t);
    cudaGetSymbolAddress((void**)&pff, g_ff);
    cudaGetSymbolAddress((void**)&pxs, g_xs);

    cudaFuncSetAttribute(mma_gemm,   cudaFuncAttributeMaxDynamicSharedMemorySize, MMAG_SMEM);
    cudaFuncSetAttribute(flash_attn, cudaFuncAttributeMaxDynamicSharedMemorySize, FL_SMEM);

    embed_kernel<<<NTOK, DIMD>>>(src, tint, emb, timeW, timeb);
    social_kernel<<<NTOK, DIMD>>>(src, nidx, ncnt, socW, socb, socg, socbe);

    mma_gemm<<<dim3(HID / 128, NTOK / 128), 256, MMAG_SMEM>>>(pxs, projW, projb, ph,
                                                              NTOK, HID, DIMD, 0);

    for (int l = 0; l < NLAYER; l++) {
        const float* Wql = Wq + (size_t)l * HID * HID; const float* bql = bq + l * HID;
        const float* Wkl = Wk + (size_t)l * HID * HID; const float* bkl = bk + l * HID;
        const float* Wvl = Wv + (size_t)l * HID * HID; const float* bvl = bv + l * HID;
        const float* Wol = Wo + (size_t)l * HID * HID; const float* bol = bo + l * HID;

        mma_gemm<<<dim3(HID / 128, NTOK / 128), 256, MMAG_SMEM>>>(ph, Wql, bql, pq,
                                                                  NTOK, HID, HID, 0);
        mma_gemm<<<dim3(HID / 128, NTOK / 128), 256, MMAG_SMEM>>>(ph, Wkl, bkl, pk,
                                                                  NTOK, HID, HID, 0);
        mma_gemm<<<dim3(HID / 128, NTOK / 128), 256, MMAG_SMEM>>>(ph, Wvl, bvl, pv,
                                                                  NTOK, HID, HID, 0);

        flash_attn<<<dim3(SEQ / 128, BATCH * NHEAD), 256, FL_SMEM>>>(src);

        mma_gemm<<<dim3(HID / 128, NTOK / 128), 256, MMAG_SMEM>>>(po, Wol, bol, pt,
                                                                  NTOK, HID, HID, 0);
        add_ln_kernel<<<NTOK, HID>>>(ph, pt, ln1g + (size_t)l * HID, ln1b + (size_t)l * HID);

        mma_gemm<<<dim3(PFF / 128, NTOK / 128), 256, MMAG_SMEM>>>(ph, ffW1 + (size_t)l * HID * PFF,
                                                                  ffb1 + (size_t)l * PFF, pff,
                                                                  NTOK, PFF, HID, 1);
        mma_gemm<<<dim3(HID / 128, NTOK / 128), 256, MMAG_SMEM>>>(pff, ffW2 + (size_t)l * PFF * HID,
                                                                  ffb2 + (size_t)l * HID, pt,
                                                                  NTOK, HID, PFF, 0);
        add_ln_kernel<<<NTOK, HID>>>(ph, pt, ln2g + (size_t)l * HID, ln2b + (size_t)l * HID);
    }

    cudaMemcpyAsync(out, ph, (size_t)NTOK * HID * sizeof(float),
                    cudaMemcpyDeviceToDevice, 0);
    if (out_size >= NTOK * (HID + DIMD)) {
        cudaMemcpyAsync(out + (size_t)NTOK * HID, pxs,
                        (size_t)NTOK * DIMD * sizeof(float),
                        cudaMemcpyDeviceToDevice, 0);
    }
}